// round 14
// baseline (speedup 1.0000x reference)
#include <cuda_runtime.h>
#include <cuda_bf16.h>
#include <cstdint>
#include <math.h>

// Problem dims
#define BATCH 64
#define SEQ   256
#define DIM   384
#define NHEAD 6
#define HDIM  64
#define NTOK  (BATCH * SEQ)      // 16384
#define FFDIM (4 * DIM)          // 1536

// ---------------- scratch (static device globals; no allocation) -------------
__device__ __nv_bfloat16 g_hb [NTOK * DIM];
__device__ float         g_q  [NTOK * DIM];
__device__ float         g_k  [NTOK * DIM];
__device__ float         g_v  [NTOK * DIM];
__device__ __nv_bfloat16 g_ctxb[NTOK * DIM];
__device__ float         g_x1 [NTOK * DIM];
__device__ __nv_bfloat16 g_ffb[NTOK * FFDIM];
__device__ __nv_bfloat16 g_wqT[DIM * DIM];
__device__ __nv_bfloat16 g_wkT[DIM * DIM];
__device__ __nv_bfloat16 g_wvT[DIM * DIM];
__device__ __nv_bfloat16 g_woT[DIM * DIM];
__device__ __nv_bfloat16 g_w1T[DIM * FFDIM];
__device__ __nv_bfloat16 g_w2T[FFDIM * DIM];

// ---------------- PTX helpers -------------------------------------------------
__device__ __forceinline__ uint32_t smem_u32(const void* p) {
    uint32_t a;
    asm("{ .reg .u64 t; cvta.to.shared.u64 t, %1; cvt.u32.u64 %0, t; }"
        : "=r"(a) : "l"(p));
    return a;
}
__device__ __forceinline__ void cp_async16(uint32_t dst, const void* src) {
    asm volatile("cp.async.cg.shared.global [%0], [%1], 16;" :: "r"(dst), "l"(src));
}
__device__ __forceinline__ void cp_commit() {
    asm volatile("cp.async.commit_group;" ::: "memory");
}
template<int N> __device__ __forceinline__ void cp_wait() {
    asm volatile("cp.async.wait_group %0;" :: "n"(N) : "memory");
}
__device__ __forceinline__ void mma_tf32(float* c, const uint32_t* a, const uint32_t* b) {
    asm volatile(
        "mma.sync.aligned.m16n8k8.row.col.f32.tf32.tf32.f32 "
        "{%0,%1,%2,%3}, {%4,%5,%6,%7}, {%8,%9}, {%0,%1,%2,%3};"
        : "+f"(c[0]), "+f"(c[1]), "+f"(c[2]), "+f"(c[3])
        : "r"(a[0]), "r"(a[1]), "r"(a[2]), "r"(a[3]), "r"(b[0]), "r"(b[1]));
}
__device__ __forceinline__ void mma_bf16(float* c, const uint32_t* a, const uint32_t* b) {
    asm volatile(
        "mma.sync.aligned.m16n8k16.row.col.f32.bf16.bf16.f32 "
        "{%0,%1,%2,%3}, {%4,%5,%6,%7}, {%8,%9}, {%0,%1,%2,%3};"
        : "+f"(c[0]), "+f"(c[1]), "+f"(c[2]), "+f"(c[3])
        : "r"(a[0]), "r"(a[1]), "r"(a[2]), "r"(a[3]), "r"(b[0]), "r"(b[1]));
}
__device__ __forceinline__ void ldsm_x4(uint32_t& r0, uint32_t& r1, uint32_t& r2,
                                        uint32_t& r3, uint32_t addr) {
    asm volatile("ldmatrix.sync.aligned.m8n8.x4.shared.b16 {%0,%1,%2,%3}, [%4];"
                 : "=r"(r0), "=r"(r1), "=r"(r2), "=r"(r3) : "r"(addr));
}
__device__ __forceinline__ uint32_t lds32(uint32_t addr) {
    uint32_t v;
    asm volatile("ld.shared.b32 %0, [%1];" : "=r"(v) : "r"(addr));
    return v;
}
__device__ __forceinline__ float ex2f(float x) {
    float y;
    asm("ex2.approx.f32 %0, %1;" : "=f"(y) : "f"(x));
    return y;
}

// ================= bf16 mma.sync GEMM, BK=64, cp.async 3-stage ===============
// 128x128 tile, 8 warps (2x4), warp tile 64x32.
#define BK       64
#define STRD2    144                       // bytes per bf16 smem row (64 bf16 + pad)
#define SA_BYTES (128 * STRD2)             // 18432
#define SB_BYTES (128 * STRD2)             // 18432
#define STAGE_BYTES (SA_BYTES + SB_BYTES)  // 36864
#define STAGES   3
#define GEMM_SMEM (STAGES * STAGE_BYTES)   // 110592

template<bool RELU, bool BIAS, bool RESID, bool OUT16>
__device__ __forceinline__ void gemm_body(
    uint32_t sb,
    const __nv_bfloat16* __restrict__ A, const __nv_bfloat16* __restrict__ WT,
    const float* __restrict__ bias, const float* __restrict__ resid,
    void* __restrict__ Cv, int K, int M, int row0, int col0, float cscale)
{
    const int tid  = threadIdx.x;
    const int wid  = tid >> 5;
    const int lane = tid & 31;
    const int warpM = wid & 1;
    const int warpN = wid >> 1;
    const int g = lane >> 2, t = lane & 3;

    const int laneRowA = ((lane >> 3) & 1) * 8 + (lane & 7);
    const int laneKA   = (lane >> 4) * 16;
    const int laneRowB = (lane >> 4) * 8 + (lane & 7);
    const int laneKB   = ((lane >> 3) & 1) * 16;

    float acc[4][4][4];
#pragma unroll
    for (int mt = 0; mt < 4; mt++)
#pragma unroll
        for (int nt = 0; nt < 4; nt++)
#pragma unroll
            for (int f = 0; f < 4; f++) acc[mt][nt][f] = 0.f;

    const int KT = K >> 6;

    auto copy_stage = [&](int kt, int st) {
        const int k0 = kt << 6;
        const uint32_t abase = sb + st * STAGE_BYTES;
        const uint32_t bbase = abase + SA_BYTES;
#pragma unroll
        for (int i = 0; i < 4; i++) {
            int c = tid + (i << 8);
            int r = c >> 3, sgm = c & 7;
            cp_async16(abase + r * STRD2 + (sgm << 4),
                       &A[(size_t)(row0 + r) * K + k0 + (sgm << 3)]);
        }
#pragma unroll
        for (int i = 0; i < 4; i++) {
            int c = tid + (i << 8);
            int n = c >> 3, sgm = c & 7;
            cp_async16(bbase + n * STRD2 + (sgm << 4),
                       &WT[(size_t)(col0 + n) * K + k0 + (sgm << 3)]);
        }
    };

    copy_stage(0, 0); cp_commit();
    copy_stage(1, 1); cp_commit();

    for (int kt = 0; kt < KT; kt++) {
        const int st = kt % STAGES;
        cp_wait<1>();
        __syncthreads();
        if (kt + 2 < KT) copy_stage(kt + 2, (kt + 2) % STAGES);
        cp_commit();

        const uint32_t aB = sb + st * STAGE_BYTES
                          + (warpM * 64 + laneRowA) * STRD2 + laneKA;
        const uint32_t bB = sb + st * STAGE_BYTES + SA_BYTES
                          + (warpN * 32 + laneRowB) * STRD2 + laneKB;
#pragma unroll
        for (int kc = 0; kc < 4; kc++) {
            uint32_t a_[4][4], b_[4][2];
#pragma unroll
            for (int mt = 0; mt < 4; mt++)
                ldsm_x4(a_[mt][0], a_[mt][1], a_[mt][2], a_[mt][3],
                        aB + mt * 16 * STRD2 + (kc << 5));
#pragma unroll
            for (int p = 0; p < 2; p++)
                ldsm_x4(b_[2 * p][0], b_[2 * p][1], b_[2 * p + 1][0], b_[2 * p + 1][1],
                        bB + p * 16 * STRD2 + (kc << 5));
#pragma unroll
            for (int mt = 0; mt < 4; mt++)
#pragma unroll
                for (int nt = 0; nt < 4; nt++)
                    mma_bf16(acc[mt][nt], a_[mt], b_[nt]);
        }
    }

    float* Cf = (float*)Cv;
    __nv_bfloat16* Ch = (__nv_bfloat16*)Cv;
#pragma unroll
    for (int mt = 0; mt < 4; mt++) {
        int r_lo = row0 + warpM * 64 + mt * 16 + g;
        int r_hi = r_lo + 8;
#pragma unroll
        for (int nt = 0; nt < 4; nt++) {
            int col = col0 + warpN * 32 + nt * 8 + (t << 1);
            float2 v0 = make_float2(acc[mt][nt][0] * cscale, acc[mt][nt][1] * cscale);
            float2 v1 = make_float2(acc[mt][nt][2] * cscale, acc[mt][nt][3] * cscale);
            if (BIAS) {
                float2 bv = *(const float2*)&bias[col];
                v0.x += bv.x; v0.y += bv.y;
                v1.x += bv.x; v1.y += bv.y;
            }
            if (RESID) {
                float2 q0 = *(const float2*)&resid[(size_t)r_lo * M + col];
                float2 q1 = *(const float2*)&resid[(size_t)r_hi * M + col];
                v0.x += q0.x; v0.y += q0.y;
                v1.x += q1.x; v1.y += q1.y;
            }
            if (RELU) {
                v0.x = fmaxf(v0.x, 0.f); v0.y = fmaxf(v0.y, 0.f);
                v1.x = fmaxf(v1.x, 0.f); v1.y = fmaxf(v1.y, 0.f);
            }
            if (OUT16) {
                *(__nv_bfloat162*)&Ch[(size_t)r_lo * M + col] =
                    __floats2bfloat162_rn(v0.x, v0.y);
                *(__nv_bfloat162*)&Ch[(size_t)r_hi * M + col] =
                    __floats2bfloat162_rn(v1.x, v1.y);
            } else {
                *(float2*)&Cf[(size_t)r_lo * M + col] = v0;
                *(float2*)&Cf[(size_t)r_hi * M + col] = v1;
            }
        }
    }
}

template<bool RELU, bool BIAS, bool RESID, bool OUT16>
__global__ void __launch_bounds__(256, 2)
bf16_gemm_kernel(const __nv_bfloat16* __restrict__ A,
                 const __nv_bfloat16* __restrict__ WT,
                 const float* __restrict__ bias, const float* __restrict__ resid,
                 void* __restrict__ C, int K, int M)
{
    extern __shared__ char smem[];
    gemm_body<RELU, BIAS, RESID, OUT16>(smem_u32(smem), A, WT, bias, resid, C,
                                        K, M, blockIdx.x * 128, blockIdx.y * 128,
                                        1.0f);
}

// Fused QKV; Q pre-scaled by (1/sqrt(HDIM)) * log2(e) for exp2-domain softmax.
#define QSCALE (0.125f * 1.4426950408889634f)
__global__ void __launch_bounds__(256, 2)
qkv_gemm_kernel(const __nv_bfloat16* __restrict__ A,
                const __nv_bfloat16* __restrict__ wqT,
                const __nv_bfloat16* __restrict__ wkT,
                const __nv_bfloat16* __restrict__ wvT,
                float* __restrict__ q, float* __restrict__ k, float* __restrict__ v)
{
    extern __shared__ char smem[];
    int y = blockIdx.y;
    int sel = y / 3;
    int col0 = (y - sel * 3) * 128;
    const __nv_bfloat16* WT = (sel == 0) ? wqT : (sel == 1) ? wkT : wvT;
    float* C = (sel == 0) ? q : (sel == 1) ? k : v;
    float cscale = (sel == 0) ? QSCALE : 1.0f;
    gemm_body<false, false, false, false>(smem_u32(smem), A, WT, nullptr, nullptr,
                                          C, DIM, DIM, blockIdx.x * 128, col0,
                                          cscale);
}

// ======== 64-row-tile GEMM for the 384-CTA launches (Wo, FFN2) ===============
// Tile 64x128, 8 warps (warpM 0..1 x warpN 0..3), warp tile 32x32.
#define SA64_BYTES (64 * STRD2)                // 9216
#define STAGE64 (SA64_BYTES + SB_BYTES)        // 27648
#define GEMM64_SMEM (STAGES * STAGE64)         // 82944

template<bool RELU, bool BIAS, bool RESID, bool OUT16>
__global__ void __launch_bounds__(256, 2)
bf16_gemm64_kernel(const __nv_bfloat16* __restrict__ A,
                   const __nv_bfloat16* __restrict__ WT,
                   const float* __restrict__ bias, const float* __restrict__ resid,
                   void* __restrict__ Cv, int K, int M)
{
    extern __shared__ char smem[];
    const uint32_t sb = smem_u32(smem);
    const int row0 = blockIdx.x * 64;
    const int col0 = blockIdx.y * 128;

    const int tid  = threadIdx.x;
    const int wid  = tid >> 5;
    const int lane = tid & 31;
    const int warpM = wid & 1;
    const int warpN = wid >> 1;
    const int g = lane >> 2, t = lane & 3;

    const int laneRowA = ((lane >> 3) & 1) * 8 + (lane & 7);
    const int laneKA   = (lane >> 4) * 16;
    const int laneRowB = (lane >> 4) * 8 + (lane & 7);
    const int laneKB   = ((lane >> 3) & 1) * 16;

    float acc[2][4][4];
#pragma unroll
    for (int mt = 0; mt < 2; mt++)
#pragma unroll
        for (int nt = 0; nt < 4; nt++)
#pragma unroll
            for (int f = 0; f < 4; f++) acc[mt][nt][f] = 0.f;

    const int KT = K >> 6;

    auto copy_stage = [&](int kt, int st) {
        const int k0 = kt << 6;
        const uint32_t abase = sb + st * STAGE64;
        const uint32_t bbase = abase + SA64_BYTES;
#pragma unroll
        for (int i = 0; i < 2; i++) {
            int c = tid + (i << 8);                // [0,512)
            int r = c >> 3, sgm = c & 7;
            cp_async16(abase + r * STRD2 + (sgm << 4),
                       &A[(size_t)(row0 + r) * K + k0 + (sgm << 3)]);
        }
#pragma unroll
        for (int i = 0; i < 4; i++) {
            int c = tid + (i << 8);                // [0,1024)
            int n = c >> 3, sgm = c & 7;
            cp_async16(bbase + n * STRD2 + (sgm << 4),
                       &WT[(size_t)(col0 + n) * K + k0 + (sgm << 3)]);
        }
    };

    copy_stage(0, 0); cp_commit();
    copy_stage(1, 1); cp_commit();

    for (int kt = 0; kt < KT; kt++) {
        const int st = kt % STAGES;
        cp_wait<1>();
        __syncthreads();
        if (kt + 2 < KT) copy_stage(kt + 2, (kt + 2) % STAGES);
        cp_commit();

        const uint32_t aB = sb + st * STAGE64
                          + (warpM * 32 + laneRowA) * STRD2 + laneKA;
        const uint32_t bB = sb + st * STAGE64 + SA64_BYTES
                          + (warpN * 32 + laneRowB) * STRD2 + laneKB;
#pragma unroll
        for (int kc = 0; kc < 4; kc++) {
            uint32_t a_[2][4], b_[4][2];
#pragma unroll
            for (int mt = 0; mt < 2; mt++)
                ldsm_x4(a_[mt][0], a_[mt][1], a_[mt][2], a_[mt][3],
                        aB + mt * 16 * STRD2 + (kc << 5));
#pragma unroll
            for (int p = 0; p < 2; p++)
                ldsm_x4(b_[2 * p][0], b_[2 * p][1], b_[2 * p + 1][0], b_[2 * p + 1][1],
                        bB + p * 16 * STRD2 + (kc << 5));
#pragma unroll
            for (int mt = 0; mt < 2; mt++)
#pragma unroll
                for (int nt = 0; nt < 4; nt++)
                    mma_bf16(acc[mt][nt], a_[mt], b_[nt]);
        }
    }

    float* Cf = (float*)Cv;
    __nv_bfloat16* Ch = (__nv_bfloat16*)Cv;
#pragma unroll
    for (int mt = 0; mt < 2; mt++) {
        int r_lo = row0 + warpM * 32 + mt * 16 + g;
        int r_hi = r_lo + 8;
#pragma unroll
        for (int nt = 0; nt < 4; nt++) {
            int col = col0 + warpN * 32 + nt * 8 + (t << 1);
            float2 v0 = make_float2(acc[mt][nt][0], acc[mt][nt][1]);
            float2 v1 = make_float2(acc[mt][nt][2], acc[mt][nt][3]);
            if (BIAS) {
                float2 bv = *(const float2*)&bias[col];
                v0.x += bv.x; v0.y += bv.y;
                v1.x += bv.x; v1.y += bv.y;
            }
            if (RESID) {
                float2 q0 = *(const float2*)&resid[(size_t)r_lo * M + col];
                float2 q1 = *(const float2*)&resid[(size_t)r_hi * M + col];
                v0.x += q0.x; v0.y += q0.y;
                v1.x += q1.x; v1.y += q1.y;
            }
            if (RELU) {
                v0.x = fmaxf(v0.x, 0.f); v0.y = fmaxf(v0.y, 0.f);
                v1.x = fmaxf(v1.x, 0.f); v1.y = fmaxf(v1.y, 0.f);
            }
            if (OUT16) {
                *(__nv_bfloat162*)&Ch[(size_t)r_lo * M + col] =
                    __floats2bfloat162_rn(v0.x, v0.y);
                *(__nv_bfloat162*)&Ch[(size_t)r_hi * M + col] =
                    __floats2bfloat162_rn(v1.x, v1.y);
            } else {
                *(float2*)&Cf[(size_t)r_lo * M + col] = v0;
                *(float2*)&Cf[(size_t)r_hi * M + col] = v1;
            }
        }
    }
}

// ======== merged prologue: weight transpose (blocks 0..1727) + LN1 ============
__global__ void prologue_kernel(
    const float* __restrict__ x, const float* __restrict__ g1,
    const float* __restrict__ be1, __nv_bfloat16* __restrict__ hb,
    const float* __restrict__ wq, const float* __restrict__ wk,
    const float* __restrict__ wv, const float* __restrict__ wo,
    const float* __restrict__ w1, const float* __restrict__ w2,
    __nv_bfloat16* __restrict__ wqT, __nv_bfloat16* __restrict__ wkT,
    __nv_bfloat16* __restrict__ wvT, __nv_bfloat16* __restrict__ woT,
    __nv_bfloat16* __restrict__ w1T, __nv_bfloat16* __restrict__ w2T)
{
    if (blockIdx.x < 1728) {
        // ---- transpose tile ----
        __shared__ float tbuf[32][33];
        int id = blockIdx.x;
        int tx = threadIdx.x & 31, ty = threadIdx.x >> 5;  // (32,8)
        const float* in; __nv_bfloat16* out; int R, C, bx, by;
        if (id < 576) {
            int m = id / 144, r = id - m * 144;
            switch (m) {
                case 0: in = wq; out = wqT; break;
                case 1: in = wk; out = wkT; break;
                case 2: in = wv; out = wvT; break;
                default: in = wo; out = woT; break;
            }
            R = DIM; C = DIM; bx = (r % 12) * 32; by = (r / 12) * 32;
        } else if (id < 1152) {
            int r = id - 576;
            in = w1; out = w1T; R = DIM; C = FFDIM;
            bx = (r % 48) * 32; by = (r / 48) * 32;
        } else {
            int r = id - 1152;
            in = w2; out = w2T; R = FFDIM; C = DIM;
            bx = (r % 12) * 32; by = (r / 12) * 32;
        }
#pragma unroll
        for (int i = 0; i < 32; i += 8)
            tbuf[ty + i][tx] = in[(size_t)(by + ty + i) * C + bx + tx];
        __syncthreads();
#pragma unroll
        for (int i = 0; i < 32; i += 8)
            out[(size_t)(bx + ty + i) * R + by + tx] =
                __float2bfloat16_rn(tbuf[tx][ty + i]);
    } else {
        // ---- LN rows ----
        int warp = ((blockIdx.x - 1728) * blockDim.x + threadIdx.x) >> 5;
        int lane = threadIdx.x & 31;
        if (warp >= NTOK) return;
        const float4* row = (const float4*)(x + (size_t)warp * DIM);
        float4 v[3];
        float s = 0.f, ss = 0.f;
#pragma unroll
        for (int i = 0; i < 3; i++) {
            v[i] = row[lane + 32 * i];
            s  += v[i].x + v[i].y + v[i].z + v[i].w;
            ss += v[i].x * v[i].x + v[i].y * v[i].y + v[i].z * v[i].z + v[i].w * v[i].w;
        }
#pragma unroll
        for (int o = 16; o; o >>= 1) {
            s  += __shfl_xor_sync(0xffffffffu, s, o);
            ss += __shfl_xor_sync(0xffffffffu, ss, o);
        }
        float mean = s * (1.0f / DIM);
        float var  = ss * (1.0f / DIM) - mean * mean;
        float rstd = rsqrtf(var + 1e-5f);
        __nv_bfloat16* orow = hb + (size_t)warp * DIM;
#pragma unroll
        for (int i = 0; i < 3; i++) {
            int c4 = lane + 32 * i;
            float4 gv = *(const float4*)&g1[c4 * 4];
            float4 bv = *(const float4*)&be1[c4 * 4];
            float ox = (v[i].x - mean) * rstd * gv.x + bv.x;
            float oy = (v[i].y - mean) * rstd * gv.y + bv.y;
            float oz = (v[i].z - mean) * rstd * gv.z + bv.z;
            float ow = (v[i].w - mean) * rstd * gv.w + bv.w;
            *(__nv_bfloat162*)&orow[c4 * 4]     = __floats2bfloat162_rn(ox, oy);
            *(__nv_bfloat162*)&orow[c4 * 4 + 2] = __floats2bfloat162_rn(oz, ow);
        }
    }
}

// ---------------- LayerNorm (LN2 only) ----------------------------------------
__global__ void ln_kernel(const float* __restrict__ x,
                          const float* __restrict__ g,
                          const float* __restrict__ be,
                          __nv_bfloat16* __restrict__ out)
{
    int warp = (blockIdx.x * blockDim.x + threadIdx.x) >> 5;
    int lane = threadIdx.x & 31;
    if (warp >= NTOK) return;
    const float4* row = (const float4*)(x + (size_t)warp * DIM);
    float4 v[3];
    float s = 0.f, ss = 0.f;
#pragma unroll
    for (int i = 0; i < 3; i++) {
        v[i] = row[lane + 32 * i];
        s  += v[i].x + v[i].y + v[i].z + v[i].w;
        ss += v[i].x * v[i].x + v[i].y * v[i].y + v[i].z * v[i].z + v[i].w * v[i].w;
    }
#pragma unroll
    for (int o = 16; o; o >>= 1) {
        s  += __shfl_xor_sync(0xffffffffu, s, o);
        ss += __shfl_xor_sync(0xffffffffu, ss, o);
    }
    float mean = s * (1.0f / DIM);
    float var  = ss * (1.0f / DIM) - mean * mean;
    float rstd = rsqrtf(var + 1e-5f);
    __nv_bfloat16* orow = out + (size_t)warp * DIM;
#pragma unroll
    for (int i = 0; i < 3; i++) {
        int c4 = lane + 32 * i;
        float4 gv = *(const float4*)&g[c4 * 4];
        float4 bv = *(const float4*)&be[c4 * 4];
        float ox = (v[i].x - mean) * rstd * gv.x + bv.x;
        float oy = (v[i].y - mean) * rstd * gv.y + bv.y;
        float oz = (v[i].z - mean) * rstd * gv.z + bv.z;
        float ow = (v[i].w - mean) * rstd * gv.w + bv.w;
        *(__nv_bfloat162*)&orow[c4 * 4]     = __floats2bfloat162_rn(ox, oy);
        *(__nv_bfloat162*)&orow[c4 * 4 + 2] = __floats2bfloat162_rn(oz, ow);
    }
}

// ---------------- Tensor-core causal flash attention (tf32, bf16 out) ---------
// exp2-domain softmax (Q pre-scaled by 0.125*log2e). Heavy qt tiles first.
#define AT_RS    68
#define AT_RB    (AT_RS * 4)               // 272
#define AT_VRB   (72 * 4)                  // 288
#define AT_KTILE (64 * AT_RB)              // 17408
#define AT_VTILE (64 * AT_VRB)             // 18432
#define AT_STAGE (AT_KTILE + AT_VTILE)     // 35840
#define ATTN_SMEM (2 * AT_STAGE)           // 71680

__global__ void __launch_bounds__(128, 3)
attn_mma_kernel(const float* __restrict__ q, const float* __restrict__ k,
                const float* __restrict__ v, __nv_bfloat16* __restrict__ ctx)
{
    extern __shared__ float sm[];
    const uint32_t sb = smem_u32(sm);

    const int qt = (SEQ / 64 - 1) - blockIdx.x;   // heaviest CTAs launch first
    const int h  = blockIdx.y;
    const int b  = blockIdx.z;
    const int tid = threadIdx.x;
    const int wid = tid >> 5;
    const int lane = tid & 31;
    const int g = lane >> 2, t = lane & 3;
    const int w16 = wid * 16;

    const int laneRowA = ((lane >> 3) & 1) * 8 + (lane & 7);
    const int laneKA   = (lane >> 4) * 16;
    const int laneRowB = (lane >> 4) * 8 + (lane & 7);
    const int laneKB   = ((lane >> 3) & 1) * 16;

    const float* qbase = q + (size_t)b * SEQ * DIM + h * HDIM;
    const float* kbase = k + (size_t)b * SEQ * DIM + h * HDIM;
    const float* vbase = v + (size_t)b * SEQ * DIM + h * HDIM;

    auto stage_off = [&](int st) -> uint32_t {
        return st ? 0u : (uint32_t)AT_STAGE;
    };

#pragma unroll
    for (int i = 0; i < 8; i++) {
        int f = tid + (i << 7);
        int r = f >> 4, d4 = (f & 15) << 2;
        cp_async16(sb + r * AT_RB + (d4 << 2),
                   &qbase[(size_t)(qt * 64 + r) * DIM + d4]);
    }
    auto copy_kv = [&](int kt, int st) {
        const uint32_t kdst = sb + stage_off(st);
        const uint32_t vdst = kdst + AT_KTILE;
#pragma unroll
        for (int i = 0; i < 8; i++) {
            int f = tid + (i << 7);
            int r = f >> 4, d4 = (f & 15) << 2;
            cp_async16(kdst + r * AT_RB + (d4 << 2),
                       &kbase[(size_t)(kt * 64 + r) * DIM + d4]);
        }
#pragma unroll
        for (int i = 0; i < 8; i++) {
            int f = tid + (i << 7);
            int r = f >> 4, d4 = (f & 15) << 2;
            cp_async16(vdst + r * AT_VRB + (d4 << 2),
                       &vbase[(size_t)(kt * 64 + r) * DIM + d4]);
        }
    };

    copy_kv(0, 0);
    cp_commit();
    cp_wait<0>();
    __syncthreads();

    uint32_t qfrag[8][4];
    {
        const uint32_t aQ = sb + (w16 + laneRowA) * AT_RB + laneKA;
#pragma unroll
        for (int kc = 0; kc < 8; kc++)
            ldsm_x4(qfrag[kc][0], qfrag[kc][1], qfrag[kc][2], qfrag[kc][3],
                    aQ + (kc << 5));
    }
    __syncthreads();

    float m0 = -1e30f, m1 = -1e30f, l0 = 0.f, l1 = 0.f;
    float accO[8][4];
#pragma unroll
    for (int nt = 0; nt < 8; nt++)
#pragma unroll
        for (int f = 0; f < 4; f++) accO[nt][f] = 0.f;

    const int r0loc = w16 + g;
    const int src_lo = (lane & ~3) | (t >> 1);
    const int src_hi = src_lo + 2;

    const int KT = qt + 1;
    for (int kt = 0; kt < KT; kt++) {
        const int st = kt & 1;
        if (kt > 0) {
            cp_wait<0>();
            __syncthreads();
        }
        if (kt + 1 < KT) {
            copy_kv(kt + 1, st ^ 1);
            cp_commit();
        }

        float accS[8][4];
#pragma unroll
        for (int nt = 0; nt < 8; nt++)
#pragma unroll
            for (int f = 0; f < 4; f++) accS[nt][f] = 0.f;

        const uint32_t bK = sb + stage_off(st) + laneRowB * AT_RB + laneKB;
#pragma unroll
        for (int kc = 0; kc < 8; kc++) {
            uint32_t b_[8][2];
#pragma unroll
            for (int p = 0; p < 4; p++)
                ldsm_x4(b_[2 * p][0], b_[2 * p][1], b_[2 * p + 1][0], b_[2 * p + 1][1],
                        bK + p * 16 * AT_RB + (kc << 5));
#pragma unroll
            for (int nt = 0; nt < 8; nt++)
                mma_tf32(accS[nt], qfrag[kc], b_[nt]);
        }

        if (kt == qt) {
#pragma unroll
            for (int nt = 0; nt < 8; nt++) {
                int c = nt * 8 + (t << 1);
                accS[nt][0] = (c     > r0loc)     ? -1e30f : accS[nt][0];
                accS[nt][1] = (c + 1 > r0loc)     ? -1e30f : accS[nt][1];
                accS[nt][2] = (c     > r0loc + 8) ? -1e30f : accS[nt][2];
                accS[nt][3] = (c + 1 > r0loc + 8) ? -1e30f : accS[nt][3];
            }
        }

        float pm0 = -1e30f, pm1 = -1e30f;
#pragma unroll
        for (int nt = 0; nt < 8; nt++) {
            pm0 = fmaxf(pm0, fmaxf(accS[nt][0], accS[nt][1]));
            pm1 = fmaxf(pm1, fmaxf(accS[nt][2], accS[nt][3]));
        }
        pm0 = fmaxf(pm0, __shfl_xor_sync(0xffffffffu, pm0, 1));
        pm0 = fmaxf(pm0, __shfl_xor_sync(0xffffffffu, pm0, 2));
        pm1 = fmaxf(pm1, __shfl_xor_sync(0xffffffffu, pm1, 1));
        pm1 = fmaxf(pm1, __shfl_xor_sync(0xffffffffu, pm1, 2));
        float mn0 = fmaxf(m0, pm0), mn1 = fmaxf(m1, pm1);
        float al0 = ex2f(m0 - mn0), al1 = ex2f(m1 - mn1);
        m0 = mn0; m1 = mn1;
        float sum0 = 0.f, sum1 = 0.f;
#pragma unroll
        for (int nt = 0; nt < 8; nt++) {
            accS[nt][0] = ex2f(accS[nt][0] - mn0);
            accS[nt][1] = ex2f(accS[nt][1] - mn0);
            accS[nt][2] = ex2f(accS[nt][2] - mn1);
            accS[nt][3] = ex2f(accS[nt][3] - mn1);
            sum0 += accS[nt][0] + accS[nt][1];
            sum1 += accS[nt][2] + accS[nt][3];
        }
        sum0 += __shfl_xor_sync(0xffffffffu, sum0, 1);
        sum0 += __shfl_xor_sync(0xffffffffu, sum0, 2);
        sum1 += __shfl_xor_sync(0xffffffffu, sum1, 1);
        sum1 += __shfl_xor_sync(0xffffffffu, sum1, 2);
        l0 = l0 * al0 + sum0;
        l1 = l1 * al1 + sum1;

#pragma unroll
        for (int nt = 0; nt < 8; nt++) {
            accO[nt][0] *= al0; accO[nt][1] *= al0;
            accO[nt][2] *= al1; accO[nt][3] *= al1;
        }
        const uint32_t bV = sb + stage_off(st) + AT_KTILE
                          + t * AT_VRB + (g << 2);
#pragma unroll
        for (int kc = 0; kc < 8; kc++) {
            float x0 = __shfl_sync(0xffffffffu, accS[kc][0], src_lo);
            float x1 = __shfl_sync(0xffffffffu, accS[kc][1], src_lo);
            float y0 = __shfl_sync(0xffffffffu, accS[kc][0], src_hi);
            float y1 = __shfl_sync(0xffffffffu, accS[kc][1], src_hi);
            float z0 = __shfl_sync(0xffffffffu, accS[kc][2], src_lo);
            float z1 = __shfl_sync(0xffffffffu, accS[kc][3], src_lo);
            float u0 = __shfl_sync(0xffffffffu, accS[kc][2], src_hi);
            float u1 = __shfl_sync(0xffffffffu, accS[kc][3], src_hi);
            uint32_t a_[4];
            a_[0] = __float_as_uint((t & 1) ? x1 : x0);
            a_[1] = __float_as_uint((t & 1) ? z1 : z0);
            a_[2] = __float_as_uint((t & 1) ? y1 : y0);
            a_[3] = __float_as_uint((t & 1) ? u1 : u0);
#pragma unroll
            for (int nt = 0; nt < 8; nt++) {
                uint32_t b_[2];
                uint32_t ba = bV + kc * 8 * AT_VRB + (nt << 5);
                b_[0] = lds32(ba);
                b_[1] = lds32(ba + 4 * AT_VRB);
                mma_tf32(accO[nt], a_, b_);
            }
        }
    }

    {
        const int r0 = w16 + g, r1 = r0 + 8;
        float inv0 = 1.0f / l0;
        float inv1 = 1.0f / l1;
        __nv_bfloat16* obase = ctx + (size_t)b * SEQ * DIM + h * HDIM;
        __nv_bfloat16* o0 = &obase[(size_t)(qt * 64 + r0) * DIM];
        __nv_bfloat16* o1 = &obase[(size_t)(qt * 64 + r1) * DIM];
#pragma unroll
        for (int nt = 0; nt < 8; nt++) {
            int c = nt * 8 + (t << 1);
            *(__nv_bfloat162*)&o0[c] =
                __floats2bfloat162_rn(accO[nt][0] * inv0, accO[nt][1] * inv0);
            *(__nv_bfloat162*)&o1[c] =
                __floats2bfloat162_rn(accO[nt][2] * inv1, accO[nt][3] * inv1);
        }
    }
}

// ---------------- launch ------------------------------------------------------
template<typename T>
static T* dev_ptr_t(const void* sym)
{
    void* p = nullptr;
    cudaGetSymbolAddress(&p, sym);
    return (T*)p;
}

extern "C" void kernel_launch(void* const* d_in, const int* in_sizes, int n_in,
                              void* d_out, int out_size)
{
    (void)in_sizes; (void)n_in; (void)out_size;
    const float* x   = (const float*)d_in[0];
    const float* wq  = (const float*)d_in[1];
    const float* wk  = (const float*)d_in[2];
    const float* wv  = (const float*)d_in[3];
    const float* wo  = (const float*)d_in[4];
    const float* bo  = (const float*)d_in[5];
    const float* w1  = (const float*)d_in[6];
    const float* b1  = (const float*)d_in[7];
    const float* w2  = (const float*)d_in[8];
    const float* b2  = (const float*)d_in[9];
    const float* g1  = (const float*)d_in[10];
    const float* be1 = (const float*)d_in[11];
    const float* g2  = (const float*)d_in[12];
    const float* be2 = (const float*)d_in[13];
    float* out = (float*)d_out;

    __nv_bfloat16* hb  = dev_ptr_t<__nv_bfloat16>(g_hb);
    float* qb          = dev_ptr_t<float>(g_q);
    float* kb          = dev_ptr_t<float>(g_k);
    float* vb          = dev_ptr_t<float>(g_v);
    __nv_bfloat16* ctxb = dev_ptr_t<__nv_bfloat16>(g_ctxb);
    float* x1          = dev_ptr_t<float>(g_x1);
    __nv_bfloat16* ffb = dev_ptr_t<__nv_bfloat16>(g_ffb);
    __nv_bfloat16* wqT = dev_ptr_t<__nv_bfloat16>(g_wqT);
    __nv_bfloat16* wkT = dev_ptr_t<__nv_bfloat16>(g_wkT);
    __nv_bfloat16* wvT = dev_ptr_t<__nv_bfloat16>(g_wvT);
    __nv_bfloat16* woT = dev_ptr_t<__nv_bfloat16>(g_woT);
    __nv_bfloat16* w1T = dev_ptr_t<__nv_bfloat16>(g_w1T);
    __nv_bfloat16* w2T = dev_ptr_t<__nv_bfloat16>(g_w2T);

    cudaFuncSetAttribute(attn_mma_kernel, cudaFuncAttributeMaxDynamicSharedMemorySize, ATTN_SMEM);
    cudaFuncSetAttribute(qkv_gemm_kernel,
                         cudaFuncAttributeMaxDynamicSharedMemorySize, GEMM_SMEM);
    cudaFuncSetAttribute(bf16_gemm_kernel<true, true, false, true>,
                         cudaFuncAttributeMaxDynamicSharedMemorySize, GEMM_SMEM);
    cudaFuncSetAttribute(bf16_gemm64_kernel<false, true, true, false>,
                         cudaFuncAttributeMaxDynamicSharedMemorySize, GEMM64_SMEM);

    // prologue: weight transposes + LN1 in one launch
    prologue_kernel<<<1728 + NTOK / 8, 256>>>(x, g1, be1, hb,
                                              wq, wk, wv, wo, w1, w2,
                                              wqT, wkT, wvT, woT, w1T, w2T);
    // fused QKV projections (Q pre-scaled for exp2 softmax)
    qkv_gemm_kernel<<<dim3(NTOK / 128, 9), 256, GEMM_SMEM>>>(hb, wqT, wkT, wvT, qb, kb, vb);
    // attention
    attn_mma_kernel<<<dim3(SEQ / 64, NHEAD, BATCH), 128, ATTN_SMEM>>>(qb, kb, vb, ctxb);
    // output projection + residual (64-row tiles: 768 CTAs, better wave packing)
    bf16_gemm64_kernel<false, true, true, false><<<dim3(NTOK / 64, 3), 256, GEMM64_SMEM>>>(
        ctxb, woT, bo, x, x1, DIM, DIM);
    // LN2
    ln_kernel<<<NTOK / 8, 256>>>(x1, g2, be2, hb);
    // FFN1 (ReLU, bf16 out)
    bf16_gemm_kernel<true, true, false, true><<<dim3(NTOK / 128, 12), 256, GEMM_SMEM>>>(
        hb, w1T, b1, nullptr, ffb, DIM, FFDIM);
    // FFN2 (+residual, 64-row tiles)
    bf16_gemm64_kernel<false, true, true, false><<<dim3(NTOK / 64, 3), 256, GEMM64_SMEM>>>(
        ffb, w2T, b2, x1, out, FFDIM, DIM);
}

// round 15
// speedup vs baseline: 1.0593x; 1.0593x over previous
#include <cuda_runtime.h>
#include <cuda_bf16.h>
#include <cstdint>
#include <math.h>

// Problem dims
#define BATCH 64
#define SEQ   256
#define DIM   384
#define NHEAD 6
#define HDIM  64
#define NTOK  (BATCH * SEQ)      // 16384
#define FFDIM (4 * DIM)          // 1536

// ---------------- scratch (static device globals; no allocation) -------------
__device__ __nv_bfloat16 g_hb [NTOK * DIM];
__device__ float         g_q  [NTOK * DIM];
__device__ float         g_k  [NTOK * DIM];
__device__ float         g_v  [NTOK * DIM];
__device__ __nv_bfloat16 g_ctxb[NTOK * DIM];
__device__ float         g_x1 [NTOK * DIM];
__device__ __nv_bfloat16 g_ffb[NTOK * FFDIM];
__device__ __nv_bfloat16 g_wqT[DIM * DIM];
__device__ __nv_bfloat16 g_wkT[DIM * DIM];
__device__ __nv_bfloat16 g_wvT[DIM * DIM];
__device__ __nv_bfloat16 g_woT[DIM * DIM];
__device__ __nv_bfloat16 g_w1T[DIM * FFDIM];
__device__ __nv_bfloat16 g_w2T[FFDIM * DIM];

// ---------------- PTX helpers -------------------------------------------------
__device__ __forceinline__ uint32_t smem_u32(const void* p) {
    uint32_t a;
    asm("{ .reg .u64 t; cvta.to.shared.u64 t, %1; cvt.u32.u64 %0, t; }"
        : "=r"(a) : "l"(p));
    return a;
}
__device__ __forceinline__ void cp_async16(uint32_t dst, const void* src) {
    asm volatile("cp.async.cg.shared.global [%0], [%1], 16;" :: "r"(dst), "l"(src));
}
__device__ __forceinline__ void cp_commit() {
    asm volatile("cp.async.commit_group;" ::: "memory");
}
template<int N> __device__ __forceinline__ void cp_wait() {
    asm volatile("cp.async.wait_group %0;" :: "n"(N) : "memory");
}
__device__ __forceinline__ void mma_tf32(float* c, const uint32_t* a, const uint32_t* b) {
    asm volatile(
        "mma.sync.aligned.m16n8k8.row.col.f32.tf32.tf32.f32 "
        "{%0,%1,%2,%3}, {%4,%5,%6,%7}, {%8,%9}, {%0,%1,%2,%3};"
        : "+f"(c[0]), "+f"(c[1]), "+f"(c[2]), "+f"(c[3])
        : "r"(a[0]), "r"(a[1]), "r"(a[2]), "r"(a[3]), "r"(b[0]), "r"(b[1]));
}
__device__ __forceinline__ void mma_bf16(float* c, const uint32_t* a, const uint32_t* b) {
    asm volatile(
        "mma.sync.aligned.m16n8k16.row.col.f32.bf16.bf16.f32 "
        "{%0,%1,%2,%3}, {%4,%5,%6,%7}, {%8,%9}, {%0,%1,%2,%3};"
        : "+f"(c[0]), "+f"(c[1]), "+f"(c[2]), "+f"(c[3])
        : "r"(a[0]), "r"(a[1]), "r"(a[2]), "r"(a[3]), "r"(b[0]), "r"(b[1]));
}
__device__ __forceinline__ void ldsm_x4(uint32_t& r0, uint32_t& r1, uint32_t& r2,
                                        uint32_t& r3, uint32_t addr) {
    asm volatile("ldmatrix.sync.aligned.m8n8.x4.shared.b16 {%0,%1,%2,%3}, [%4];"
                 : "=r"(r0), "=r"(r1), "=r"(r2), "=r"(r3) : "r"(addr));
}
__device__ __forceinline__ uint32_t lds32(uint32_t addr) {
    uint32_t v;
    asm volatile("ld.shared.b32 %0, [%1];" : "=r"(v) : "r"(addr));
    return v;
}
__device__ __forceinline__ float ex2f(float x) {
    float y;
    asm("ex2.approx.f32 %0, %1;" : "=f"(y) : "f"(x));
    return y;
}

// ================= bf16 mma.sync GEMM, BK=64, cp.async 3-stage ===============
// 128x128 tile, 8 warps (2x4), warp tile 64x32.
#define BK       64
#define STRD2    144                       // bytes per bf16 smem row (64 bf16 + pad)
#define SA_BYTES (128 * STRD2)             // 18432
#define SB_BYTES (128 * STRD2)             // 18432
#define STAGE_BYTES (SA_BYTES + SB_BYTES)  // 36864
#define STAGES   3
#define GEMM_SMEM (STAGES * STAGE_BYTES)   // 110592

template<bool RELU, bool BIAS, bool RESID, bool OUT16>
__device__ __forceinline__ void gemm_body(
    uint32_t sb,
    const __nv_bfloat16* __restrict__ A, const __nv_bfloat16* __restrict__ WT,
    const float* __restrict__ bias, const float* __restrict__ resid,
    void* __restrict__ Cv, int K, int M, int row0, int col0, float cscale)
{
    const int tid  = threadIdx.x;
    const int wid  = tid >> 5;
    const int lane = tid & 31;
    const int warpM = wid & 1;
    const int warpN = wid >> 1;
    const int g = lane >> 2, t = lane & 3;

    const int laneRowA = ((lane >> 3) & 1) * 8 + (lane & 7);
    const int laneKA   = (lane >> 4) * 16;
    const int laneRowB = (lane >> 4) * 8 + (lane & 7);
    const int laneKB   = ((lane >> 3) & 1) * 16;

    float acc[4][4][4];
#pragma unroll
    for (int mt = 0; mt < 4; mt++)
#pragma unroll
        for (int nt = 0; nt < 4; nt++)
#pragma unroll
            for (int f = 0; f < 4; f++) acc[mt][nt][f] = 0.f;

    const int KT = K >> 6;

    auto copy_stage = [&](int kt, int st) {
        const int k0 = kt << 6;
        const uint32_t abase = sb + st * STAGE_BYTES;
        const uint32_t bbase = abase + SA_BYTES;
#pragma unroll
        for (int i = 0; i < 4; i++) {
            int c = tid + (i << 8);
            int r = c >> 3, sgm = c & 7;
            cp_async16(abase + r * STRD2 + (sgm << 4),
                       &A[(size_t)(row0 + r) * K + k0 + (sgm << 3)]);
        }
#pragma unroll
        for (int i = 0; i < 4; i++) {
            int c = tid + (i << 8);
            int n = c >> 3, sgm = c & 7;
            cp_async16(bbase + n * STRD2 + (sgm << 4),
                       &WT[(size_t)(col0 + n) * K + k0 + (sgm << 3)]);
        }
    };

    copy_stage(0, 0); cp_commit();
    copy_stage(1, 1); cp_commit();

    for (int kt = 0; kt < KT; kt++) {
        const int st = kt % STAGES;
        cp_wait<1>();
        __syncthreads();
        if (kt + 2 < KT) copy_stage(kt + 2, (kt + 2) % STAGES);
        cp_commit();

        const uint32_t aB = sb + st * STAGE_BYTES
                          + (warpM * 64 + laneRowA) * STRD2 + laneKA;
        const uint32_t bB = sb + st * STAGE_BYTES + SA_BYTES
                          + (warpN * 32 + laneRowB) * STRD2 + laneKB;
#pragma unroll
        for (int kc = 0; kc < 4; kc++) {
            uint32_t a_[4][4], b_[4][2];
#pragma unroll
            for (int mt = 0; mt < 4; mt++)
                ldsm_x4(a_[mt][0], a_[mt][1], a_[mt][2], a_[mt][3],
                        aB + mt * 16 * STRD2 + (kc << 5));
#pragma unroll
            for (int p = 0; p < 2; p++)
                ldsm_x4(b_[2 * p][0], b_[2 * p][1], b_[2 * p + 1][0], b_[2 * p + 1][1],
                        bB + p * 16 * STRD2 + (kc << 5));
#pragma unroll
            for (int mt = 0; mt < 4; mt++)
#pragma unroll
                for (int nt = 0; nt < 4; nt++)
                    mma_bf16(acc[mt][nt], a_[mt], b_[nt]);
        }
    }

    float* Cf = (float*)Cv;
    __nv_bfloat16* Ch = (__nv_bfloat16*)Cv;
#pragma unroll
    for (int mt = 0; mt < 4; mt++) {
        int r_lo = row0 + warpM * 64 + mt * 16 + g;
        int r_hi = r_lo + 8;
#pragma unroll
        for (int nt = 0; nt < 4; nt++) {
            int col = col0 + warpN * 32 + nt * 8 + (t << 1);
            float2 v0 = make_float2(acc[mt][nt][0] * cscale, acc[mt][nt][1] * cscale);
            float2 v1 = make_float2(acc[mt][nt][2] * cscale, acc[mt][nt][3] * cscale);
            if (BIAS) {
                float2 bv = *(const float2*)&bias[col];
                v0.x += bv.x; v0.y += bv.y;
                v1.x += bv.x; v1.y += bv.y;
            }
            if (RESID) {
                float2 q0 = *(const float2*)&resid[(size_t)r_lo * M + col];
                float2 q1 = *(const float2*)&resid[(size_t)r_hi * M + col];
                v0.x += q0.x; v0.y += q0.y;
                v1.x += q1.x; v1.y += q1.y;
            }
            if (RELU) {
                v0.x = fmaxf(v0.x, 0.f); v0.y = fmaxf(v0.y, 0.f);
                v1.x = fmaxf(v1.x, 0.f); v1.y = fmaxf(v1.y, 0.f);
            }
            if (OUT16) {
                *(__nv_bfloat162*)&Ch[(size_t)r_lo * M + col] =
                    __floats2bfloat162_rn(v0.x, v0.y);
                *(__nv_bfloat162*)&Ch[(size_t)r_hi * M + col] =
                    __floats2bfloat162_rn(v1.x, v1.y);
            } else {
                *(float2*)&Cf[(size_t)r_lo * M + col] = v0;
                *(float2*)&Cf[(size_t)r_hi * M + col] = v1;
            }
        }
    }
}

template<bool RELU, bool BIAS, bool RESID, bool OUT16>
__global__ void __launch_bounds__(256, 2)
bf16_gemm_kernel(const __nv_bfloat16* __restrict__ A,
                 const __nv_bfloat16* __restrict__ WT,
                 const float* __restrict__ bias, const float* __restrict__ resid,
                 void* __restrict__ C, int K, int M)
{
    extern __shared__ char smem[];
    gemm_body<RELU, BIAS, RESID, OUT16>(smem_u32(smem), A, WT, bias, resid, C,
                                        K, M, blockIdx.x * 128, blockIdx.y * 128,
                                        1.0f);
}

// Fused QKV; Q pre-scaled by (1/sqrt(HDIM)) * log2(e) for exp2-domain softmax.
#define QSCALE (0.125f * 1.4426950408889634f)
__global__ void __launch_bounds__(256, 2)
qkv_gemm_kernel(const __nv_bfloat16* __restrict__ A,
                const __nv_bfloat16* __restrict__ wqT,
                const __nv_bfloat16* __restrict__ wkT,
                const __nv_bfloat16* __restrict__ wvT,
                float* __restrict__ q, float* __restrict__ k, float* __restrict__ v)
{
    extern __shared__ char smem[];
    int y = blockIdx.y;
    int sel = y / 3;
    int col0 = (y - sel * 3) * 128;
    const __nv_bfloat16* WT = (sel == 0) ? wqT : (sel == 1) ? wkT : wvT;
    float* C = (sel == 0) ? q : (sel == 1) ? k : v;
    float cscale = (sel == 0) ? QSCALE : 1.0f;
    gemm_body<false, false, false, false>(smem_u32(smem), A, WT, nullptr, nullptr,
                                          C, DIM, DIM, blockIdx.x * 128, col0,
                                          cscale);
}

// ======== merged prologue: weight transpose (blocks 0..1727) + LN1 ============
__global__ void prologue_kernel(
    const float* __restrict__ x, const float* __restrict__ g1,
    const float* __restrict__ be1, __nv_bfloat16* __restrict__ hb,
    const float* __restrict__ wq, const float* __restrict__ wk,
    const float* __restrict__ wv, const float* __restrict__ wo,
    const float* __restrict__ w1, const float* __restrict__ w2,
    __nv_bfloat16* __restrict__ wqT, __nv_bfloat16* __restrict__ wkT,
    __nv_bfloat16* __restrict__ wvT, __nv_bfloat16* __restrict__ woT,
    __nv_bfloat16* __restrict__ w1T, __nv_bfloat16* __restrict__ w2T)
{
    if (blockIdx.x < 1728) {
        __shared__ float tbuf[32][33];
        int id = blockIdx.x;
        int tx = threadIdx.x & 31, ty = threadIdx.x >> 5;  // (32,8)
        const float* in; __nv_bfloat16* out; int R, C, bx, by;
        if (id < 576) {
            int m = id / 144, r = id - m * 144;
            switch (m) {
                case 0: in = wq; out = wqT; break;
                case 1: in = wk; out = wkT; break;
                case 2: in = wv; out = wvT; break;
                default: in = wo; out = woT; break;
            }
            R = DIM; C = DIM; bx = (r % 12) * 32; by = (r / 12) * 32;
        } else if (id < 1152) {
            int r = id - 576;
            in = w1; out = w1T; R = DIM; C = FFDIM;
            bx = (r % 48) * 32; by = (r / 48) * 32;
        } else {
            int r = id - 1152;
            in = w2; out = w2T; R = FFDIM; C = DIM;
            bx = (r % 12) * 32; by = (r / 12) * 32;
        }
#pragma unroll
        for (int i = 0; i < 32; i += 8)
            tbuf[ty + i][tx] = in[(size_t)(by + ty + i) * C + bx + tx];
        __syncthreads();
#pragma unroll
        for (int i = 0; i < 32; i += 8)
            out[(size_t)(bx + ty + i) * R + by + tx] =
                __float2bfloat16_rn(tbuf[tx][ty + i]);
    } else {
        int warp = ((blockIdx.x - 1728) * blockDim.x + threadIdx.x) >> 5;
        int lane = threadIdx.x & 31;
        if (warp >= NTOK) return;
        const float4* row = (const float4*)(x + (size_t)warp * DIM);
        float4 v[3];
        float s = 0.f, ss = 0.f;
#pragma unroll
        for (int i = 0; i < 3; i++) {
            v[i] = row[lane + 32 * i];
            s  += v[i].x + v[i].y + v[i].z + v[i].w;
            ss += v[i].x * v[i].x + v[i].y * v[i].y + v[i].z * v[i].z + v[i].w * v[i].w;
        }
#pragma unroll
        for (int o = 16; o; o >>= 1) {
            s  += __shfl_xor_sync(0xffffffffu, s, o);
            ss += __shfl_xor_sync(0xffffffffu, ss, o);
        }
        float mean = s * (1.0f / DIM);
        float var  = ss * (1.0f / DIM) - mean * mean;
        float rstd = rsqrtf(var + 1e-5f);
        __nv_bfloat16* orow = hb + (size_t)warp * DIM;
#pragma unroll
        for (int i = 0; i < 3; i++) {
            int c4 = lane + 32 * i;
            float4 gv = *(const float4*)&g1[c4 * 4];
            float4 bv = *(const float4*)&be1[c4 * 4];
            float ox = (v[i].x - mean) * rstd * gv.x + bv.x;
            float oy = (v[i].y - mean) * rstd * gv.y + bv.y;
            float oz = (v[i].z - mean) * rstd * gv.z + bv.z;
            float ow = (v[i].w - mean) * rstd * gv.w + bv.w;
            *(__nv_bfloat162*)&orow[c4 * 4]     = __floats2bfloat162_rn(ox, oy);
            *(__nv_bfloat162*)&orow[c4 * 4 + 2] = __floats2bfloat162_rn(oz, ow);
        }
    }
}

// ---------------- LayerNorm (LN2 only) ----------------------------------------
__global__ void ln_kernel(const float* __restrict__ x,
                          const float* __restrict__ g,
                          const float* __restrict__ be,
                          __nv_bfloat16* __restrict__ out)
{
    int warp = (blockIdx.x * blockDim.x + threadIdx.x) >> 5;
    int lane = threadIdx.x & 31;
    if (warp >= NTOK) return;
    const float4* row = (const float4*)(x + (size_t)warp * DIM);
    float4 v[3];
    float s = 0.f, ss = 0.f;
#pragma unroll
    for (int i = 0; i < 3; i++) {
        v[i] = row[lane + 32 * i];
        s  += v[i].x + v[i].y + v[i].z + v[i].w;
        ss += v[i].x * v[i].x + v[i].y * v[i].y + v[i].z * v[i].z + v[i].w * v[i].w;
    }
#pragma unroll
    for (int o = 16; o; o >>= 1) {
        s  += __shfl_xor_sync(0xffffffffu, s, o);
        ss += __shfl_xor_sync(0xffffffffu, ss, o);
    }
    float mean = s * (1.0f / DIM);
    float var  = ss * (1.0f / DIM) - mean * mean;
    float rstd = rsqrtf(var + 1e-5f);
    __nv_bfloat16* orow = out + (size_t)warp * DIM;
#pragma unroll
    for (int i = 0; i < 3; i++) {
        int c4 = lane + 32 * i;
        float4 gv = *(const float4*)&g[c4 * 4];
        float4 bv = *(const float4*)&be[c4 * 4];
        float ox = (v[i].x - mean) * rstd * gv.x + bv.x;
        float oy = (v[i].y - mean) * rstd * gv.y + bv.y;
        float oz = (v[i].z - mean) * rstd * gv.z + bv.z;
        float ow = (v[i].w - mean) * rstd * gv.w + bv.w;
        *(__nv_bfloat162*)&orow[c4 * 4]     = __floats2bfloat162_rn(ox, oy);
        *(__nv_bfloat162*)&orow[c4 * 4 + 2] = __floats2bfloat162_rn(oz, ow);
    }
}

// ---------------- Tensor-core causal flash attention (tf32, bf16 out) ---------
// exp2-domain softmax (Q pre-scaled by 0.125*log2e). Heavy qt tiles first.
#define AT_RS    68
#define AT_RB    (AT_RS * 4)               // 272
#define AT_VRB   (72 * 4)                  // 288
#define AT_KTILE (64 * AT_RB)              // 17408
#define AT_VTILE (64 * AT_VRB)             // 18432
#define AT_STAGE (AT_KTILE + AT_VTILE)     // 35840
#define ATTN_SMEM (2 * AT_STAGE)           // 71680

__global__ void __launch_bounds__(128, 3)
attn_mma_kernel(const float* __restrict__ q, const float* __restrict__ k,
                const float* __restrict__ v, __nv_bfloat16* __restrict__ ctx)
{
    extern __shared__ float sm[];
    const uint32_t sb = smem_u32(sm);

    const int qt = (SEQ / 64 - 1) - blockIdx.x;   // heaviest CTAs launch first
    const int h  = blockIdx.y;
    const int b  = blockIdx.z;
    const int tid = threadIdx.x;
    const int wid = tid >> 5;
    const int lane = tid & 31;
    const int g = lane >> 2, t = lane & 3;
    const int w16 = wid * 16;

    const int laneRowA = ((lane >> 3) & 1) * 8 + (lane & 7);
    const int laneKA   = (lane >> 4) * 16;
    const int laneRowB = (lane >> 4) * 8 + (lane & 7);
    const int laneKB   = ((lane >> 3) & 1) * 16;

    const float* qbase = q + (size_t)b * SEQ * DIM + h * HDIM;
    const float* kbase = k + (size_t)b * SEQ * DIM + h * HDIM;
    const float* vbase = v + (size_t)b * SEQ * DIM + h * HDIM;

    auto stage_off = [&](int st) -> uint32_t {
        return st ? 0u : (uint32_t)AT_STAGE;
    };

#pragma unroll
    for (int i = 0; i < 8; i++) {
        int f = tid + (i << 7);
        int r = f >> 4, d4 = (f & 15) << 2;
        cp_async16(sb + r * AT_RB + (d4 << 2),
                   &qbase[(size_t)(qt * 64 + r) * DIM + d4]);
    }
    auto copy_kv = [&](int kt, int st) {
        const uint32_t kdst = sb + stage_off(st);
        const uint32_t vdst = kdst + AT_KTILE;
#pragma unroll
        for (int i = 0; i < 8; i++) {
            int f = tid + (i << 7);
            int r = f >> 4, d4 = (f & 15) << 2;
            cp_async16(kdst + r * AT_RB + (d4 << 2),
                       &kbase[(size_t)(kt * 64 + r) * DIM + d4]);
        }
#pragma unroll
        for (int i = 0; i < 8; i++) {
            int f = tid + (i << 7);
            int r = f >> 4, d4 = (f & 15) << 2;
            cp_async16(vdst + r * AT_VRB + (d4 << 2),
                       &vbase[(size_t)(kt * 64 + r) * DIM + d4]);
        }
    };

    copy_kv(0, 0);
    cp_commit();
    cp_wait<0>();
    __syncthreads();

    uint32_t qfrag[8][4];
    {
        const uint32_t aQ = sb + (w16 + laneRowA) * AT_RB + laneKA;
#pragma unroll
        for (int kc = 0; kc < 8; kc++)
            ldsm_x4(qfrag[kc][0], qfrag[kc][1], qfrag[kc][2], qfrag[kc][3],
                    aQ + (kc << 5));
    }
    __syncthreads();

    float m0 = -1e30f, m1 = -1e30f, l0 = 0.f, l1 = 0.f;
    float accO[8][4];
#pragma unroll
    for (int nt = 0; nt < 8; nt++)
#pragma unroll
        for (int f = 0; f < 4; f++) accO[nt][f] = 0.f;

    const int r0loc = w16 + g;
    const int src_lo = (lane & ~3) | (t >> 1);
    const int src_hi = src_lo + 2;

    const int KT = qt + 1;
    for (int kt = 0; kt < KT; kt++) {
        const int st = kt & 1;
        if (kt > 0) {
            cp_wait<0>();
            __syncthreads();
        }
        if (kt + 1 < KT) {
            copy_kv(kt + 1, st ^ 1);
            cp_commit();
        }

        float accS[8][4];
#pragma unroll
        for (int nt = 0; nt < 8; nt++)
#pragma unroll
            for (int f = 0; f < 4; f++) accS[nt][f] = 0.f;

        const uint32_t bK = sb + stage_off(st) + laneRowB * AT_RB + laneKB;
#pragma unroll
        for (int kc = 0; kc < 8; kc++) {
            uint32_t b_[8][2];
#pragma unroll
            for (int p = 0; p < 4; p++)
                ldsm_x4(b_[2 * p][0], b_[2 * p][1], b_[2 * p + 1][0], b_[2 * p + 1][1],
                        bK + p * 16 * AT_RB + (kc << 5));
#pragma unroll
            for (int nt = 0; nt < 8; nt++)
                mma_tf32(accS[nt], qfrag[kc], b_[nt]);
        }

        if (kt == qt) {
#pragma unroll
            for (int nt = 0; nt < 8; nt++) {
                int c = nt * 8 + (t << 1);
                accS[nt][0] = (c     > r0loc)     ? -1e30f : accS[nt][0];
                accS[nt][1] = (c + 1 > r0loc)     ? -1e30f : accS[nt][1];
                accS[nt][2] = (c     > r0loc + 8) ? -1e30f : accS[nt][2];
                accS[nt][3] = (c + 1 > r0loc + 8) ? -1e30f : accS[nt][3];
            }
        }

        float pm0 = -1e30f, pm1 = -1e30f;
#pragma unroll
        for (int nt = 0; nt < 8; nt++) {
            pm0 = fmaxf(pm0, fmaxf(accS[nt][0], accS[nt][1]));
            pm1 = fmaxf(pm1, fmaxf(accS[nt][2], accS[nt][3]));
        }
        pm0 = fmaxf(pm0, __shfl_xor_sync(0xffffffffu, pm0, 1));
        pm0 = fmaxf(pm0, __shfl_xor_sync(0xffffffffu, pm0, 2));
        pm1 = fmaxf(pm1, __shfl_xor_sync(0xffffffffu, pm1, 1));
        pm1 = fmaxf(pm1, __shfl_xor_sync(0xffffffffu, pm1, 2));
        float mn0 = fmaxf(m0, pm0), mn1 = fmaxf(m1, pm1);
        float al0 = ex2f(m0 - mn0), al1 = ex2f(m1 - mn1);
        m0 = mn0; m1 = mn1;
        float sum0 = 0.f, sum1 = 0.f;
#pragma unroll
        for (int nt = 0; nt < 8; nt++) {
            accS[nt][0] = ex2f(accS[nt][0] - mn0);
            accS[nt][1] = ex2f(accS[nt][1] - mn0);
            accS[nt][2] = ex2f(accS[nt][2] - mn1);
            accS[nt][3] = ex2f(accS[nt][3] - mn1);
            sum0 += accS[nt][0] + accS[nt][1];
            sum1 += accS[nt][2] + accS[nt][3];
        }
        sum0 += __shfl_xor_sync(0xffffffffu, sum0, 1);
        sum0 += __shfl_xor_sync(0xffffffffu, sum0, 2);
        sum1 += __shfl_xor_sync(0xffffffffu, sum1, 1);
        sum1 += __shfl_xor_sync(0xffffffffu, sum1, 2);
        l0 = l0 * al0 + sum0;
        l1 = l1 * al1 + sum1;

#pragma unroll
        for (int nt = 0; nt < 8; nt++) {
            accO[nt][0] *= al0; accO[nt][1] *= al0;
            accO[nt][2] *= al1; accO[nt][3] *= al1;
        }
        const uint32_t bV = sb + stage_off(st) + AT_KTILE
                          + t * AT_VRB + (g << 2);
#pragma unroll
        for (int kc = 0; kc < 8; kc++) {
            float x0 = __shfl_sync(0xffffffffu, accS[kc][0], src_lo);
            float x1 = __shfl_sync(0xffffffffu, accS[kc][1], src_lo);
            float y0 = __shfl_sync(0xffffffffu, accS[kc][0], src_hi);
            float y1 = __shfl_sync(0xffffffffu, accS[kc][1], src_hi);
            float z0 = __shfl_sync(0xffffffffu, accS[kc][2], src_lo);
            float z1 = __shfl_sync(0xffffffffu, accS[kc][3], src_lo);
            float u0 = __shfl_sync(0xffffffffu, accS[kc][2], src_hi);
            float u1 = __shfl_sync(0xffffffffu, accS[kc][3], src_hi);
            uint32_t a_[4];
            a_[0] = __float_as_uint((t & 1) ? x1 : x0);
            a_[1] = __float_as_uint((t & 1) ? z1 : z0);
            a_[2] = __float_as_uint((t & 1) ? y1 : y0);
            a_[3] = __float_as_uint((t & 1) ? u1 : u0);
#pragma unroll
            for (int nt = 0; nt < 8; nt++) {
                uint32_t b_[2];
                uint32_t ba = bV + kc * 8 * AT_VRB + (nt << 5);
                b_[0] = lds32(ba);
                b_[1] = lds32(ba + 4 * AT_VRB);
                mma_tf32(accO[nt], a_, b_);
            }
        }
    }

    {
        const int r0 = w16 + g, r1 = r0 + 8;
        float inv0 = 1.0f / l0;
        float inv1 = 1.0f / l1;
        __nv_bfloat16* obase = ctx + (size_t)b * SEQ * DIM + h * HDIM;
        __nv_bfloat16* o0 = &obase[(size_t)(qt * 64 + r0) * DIM];
        __nv_bfloat16* o1 = &obase[(size_t)(qt * 64 + r1) * DIM];
#pragma unroll
        for (int nt = 0; nt < 8; nt++) {
            int c = nt * 8 + (t << 1);
            *(__nv_bfloat162*)&o0[c] =
                __floats2bfloat162_rn(accO[nt][0] * inv0, accO[nt][1] * inv0);
            *(__nv_bfloat162*)&o1[c] =
                __floats2bfloat162_rn(accO[nt][2] * inv1, accO[nt][3] * inv1);
        }
    }
}

// ---------------- launch ------------------------------------------------------
template<typename T>
static T* dev_ptr_t(const void* sym)
{
    void* p = nullptr;
    cudaGetSymbolAddress(&p, sym);
    return (T*)p;
}

extern "C" void kernel_launch(void* const* d_in, const int* in_sizes, int n_in,
                              void* d_out, int out_size)
{
    (void)in_sizes; (void)n_in; (void)out_size;
    const float* x   = (const float*)d_in[0];
    const float* wq  = (const float*)d_in[1];
    const float* wk  = (const float*)d_in[2];
    const float* wv  = (const float*)d_in[3];
    const float* wo  = (const float*)d_in[4];
    const float* bo  = (const float*)d_in[5];
    const float* w1  = (const float*)d_in[6];
    const float* b1  = (const float*)d_in[7];
    const float* w2  = (const float*)d_in[8];
    const float* b2  = (const float*)d_in[9];
    const float* g1  = (const float*)d_in[10];
    const float* be1 = (const float*)d_in[11];
    const float* g2  = (const float*)d_in[12];
    const float* be2 = (const float*)d_in[13];
    float* out = (float*)d_out;

    __nv_bfloat16* hb  = dev_ptr_t<__nv_bfloat16>(g_hb);
    float* qb          = dev_ptr_t<float>(g_q);
    float* kb          = dev_ptr_t<float>(g_k);
    float* vb          = dev_ptr_t<float>(g_v);
    __nv_bfloat16* ctxb = dev_ptr_t<__nv_bfloat16>(g_ctxb);
    float* x1          = dev_ptr_t<float>(g_x1);
    __nv_bfloat16* ffb = dev_ptr_t<__nv_bfloat16>(g_ffb);
    __nv_bfloat16* wqT = dev_ptr_t<__nv_bfloat16>(g_wqT);
    __nv_bfloat16* wkT = dev_ptr_t<__nv_bfloat16>(g_wkT);
    __nv_bfloat16* wvT = dev_ptr_t<__nv_bfloat16>(g_wvT);
    __nv_bfloat16* woT = dev_ptr_t<__nv_bfloat16>(g_woT);
    __nv_bfloat16* w1T = dev_ptr_t<__nv_bfloat16>(g_w1T);
    __nv_bfloat16* w2T = dev_ptr_t<__nv_bfloat16>(g_w2T);

    cudaFuncSetAttribute(attn_mma_kernel, cudaFuncAttributeMaxDynamicSharedMemorySize, ATTN_SMEM);
    cudaFuncSetAttribute(qkv_gemm_kernel,
                         cudaFuncAttributeMaxDynamicSharedMemorySize, GEMM_SMEM);
    cudaFuncSetAttribute(bf16_gemm_kernel<false, true, true, false>,
                         cudaFuncAttributeMaxDynamicSharedMemorySize, GEMM_SMEM);
    cudaFuncSetAttribute(bf16_gemm_kernel<true, true, false, true>,
                         cudaFuncAttributeMaxDynamicSharedMemorySize, GEMM_SMEM);

    // prologue: weight transposes + LN1 in one launch
    prologue_kernel<<<1728 + NTOK / 8, 256>>>(x, g1, be1, hb,
                                              wq, wk, wv, wo, w1, w2,
                                              wqT, wkT, wvT, woT, w1T, w2T);
    // fused QKV projections (Q pre-scaled for exp2 softmax)
    qkv_gemm_kernel<<<dim3(NTOK / 128, 9), 256, GEMM_SMEM>>>(hb, wqT, wkT, wvT, qb, kb, vb);
    // attention
    attn_mma_kernel<<<dim3(SEQ / 64, NHEAD, BATCH), 128, ATTN_SMEM>>>(qb, kb, vb, ctxb);
    // output projection + residual (128x128 tiles — R14's 64-row variant reverted)
    bf16_gemm_kernel<false, true, true, false><<<dim3(NTOK / 128, 3), 256, GEMM_SMEM>>>(
        ctxb, woT, bo, x, x1, DIM, DIM);
    // LN2
    ln_kernel<<<NTOK / 8, 256>>>(x1, g2, be2, hb);
    // FFN1 (ReLU, bf16 out)
    bf16_gemm_kernel<true, true, false, true><<<dim3(NTOK / 128, 12), 256, GEMM_SMEM>>>(
        hb, w1T, b1, nullptr, ffb, DIM, FFDIM);
    // FFN2 (+residual)
    bf16_gemm_kernel<false, true, true, false><<<dim3(NTOK / 128, 3), 256, GEMM_SMEM>>>(
        ffb, w2T, b2, x1, out, FFDIM, DIM);
}

// round 16
// speedup vs baseline: 1.0645x; 1.0049x over previous
#include <cuda_runtime.h>
#include <cuda_bf16.h>
#include <cstdint>
#include <math.h>

// Problem dims
#define BATCH 64
#define SEQ   256
#define DIM   384
#define NHEAD 6
#define HDIM  64
#define NTOK  (BATCH * SEQ)      // 16384
#define FFDIM (4 * DIM)          // 1536

// ---------------- scratch (static device globals; no allocation) -------------
__device__ __nv_bfloat16 g_hb [NTOK * DIM];
__device__ float         g_q  [NTOK * DIM];
__device__ float         g_k  [NTOK * DIM];
__device__ float         g_v  [NTOK * DIM];
__device__ __nv_bfloat16 g_ctxb[NTOK * DIM];
__device__ float         g_x1 [NTOK * DIM];
__device__ __nv_bfloat16 g_ffb[NTOK * FFDIM];
__device__ __nv_bfloat16 g_wqT[DIM * DIM];
__device__ __nv_bfloat16 g_wkT[DIM * DIM];
__device__ __nv_bfloat16 g_wvT[DIM * DIM];
__device__ __nv_bfloat16 g_woT[DIM * DIM];
__device__ __nv_bfloat16 g_w1T[DIM * FFDIM];
__device__ __nv_bfloat16 g_w2T[FFDIM * DIM];

// ---------------- PTX helpers -------------------------------------------------
__device__ __forceinline__ uint32_t smem_u32(const void* p) {
    uint32_t a;
    asm("{ .reg .u64 t; cvta.to.shared.u64 t, %1; cvt.u32.u64 %0, t; }"
        : "=r"(a) : "l"(p));
    return a;
}
__device__ __forceinline__ void cp_async16(uint32_t dst, const void* src) {
    asm volatile("cp.async.cg.shared.global [%0], [%1], 16;" :: "r"(dst), "l"(src));
}
__device__ __forceinline__ void cp_commit() {
    asm volatile("cp.async.commit_group;" ::: "memory");
}
template<int N> __device__ __forceinline__ void cp_wait() {
    asm volatile("cp.async.wait_group %0;" :: "n"(N) : "memory");
}
__device__ __forceinline__ void mma_tf32(float* c, const uint32_t* a, const uint32_t* b) {
    asm volatile(
        "mma.sync.aligned.m16n8k8.row.col.f32.tf32.tf32.f32 "
        "{%0,%1,%2,%3}, {%4,%5,%6,%7}, {%8,%9}, {%0,%1,%2,%3};"
        : "+f"(c[0]), "+f"(c[1]), "+f"(c[2]), "+f"(c[3])
        : "r"(a[0]), "r"(a[1]), "r"(a[2]), "r"(a[3]), "r"(b[0]), "r"(b[1]));
}
__device__ __forceinline__ void mma_bf16(float* c, const uint32_t* a, const uint32_t* b) {
    asm volatile(
        "mma.sync.aligned.m16n8k16.row.col.f32.bf16.bf16.f32 "
        "{%0,%1,%2,%3}, {%4,%5,%6,%7}, {%8,%9}, {%0,%1,%2,%3};"
        : "+f"(c[0]), "+f"(c[1]), "+f"(c[2]), "+f"(c[3])
        : "r"(a[0]), "r"(a[1]), "r"(a[2]), "r"(a[3]), "r"(b[0]), "r"(b[1]));
}
__device__ __forceinline__ void ldsm_x4(uint32_t& r0, uint32_t& r1, uint32_t& r2,
                                        uint32_t& r3, uint32_t addr) {
    asm volatile("ldmatrix.sync.aligned.m8n8.x4.shared.b16 {%0,%1,%2,%3}, [%4];"
                 : "=r"(r0), "=r"(r1), "=r"(r2), "=r"(r3) : "r"(addr));
}
__device__ __forceinline__ uint32_t lds32(uint32_t addr) {
    uint32_t v;
    asm volatile("ld.shared.b32 %0, [%1];" : "=r"(v) : "r"(addr));
    return v;
}
__device__ __forceinline__ float ex2f(float x) {
    float y;
    asm("ex2.approx.f32 %0, %1;" : "=f"(y) : "f"(x));
    return y;
}

// ============ bf16 mma.sync GEMM, 64x128 CTA tile, 2-stage, 4 CTAs/SM ========
// A: [N,K] bf16 row-major, WT: [M,K] bf16 row-major, C = act(A@W+bias+resid).
// CTA 64 rows x 128 cols, BK=64, 128 threads = 4 warps; each warp keeps the
// proven 64x32 tile (warpN = wid). 2-stage cp.async pipeline; 4 independent
// CTA pipelines per SM cover the cp.async latency that 2 could not.
#define BK       64
#define STRD2    144                       // bytes per bf16 smem row (64 bf16 + pad)
#define SA_BYTES (64 * STRD2)              // 9216
#define SB_BYTES (128 * STRD2)             // 18432
#define STAGE_BYTES (SA_BYTES + SB_BYTES)  // 27648
#define GEMM_SMEM (2 * STAGE_BYTES)        // 55296

template<bool RELU, bool BIAS, bool RESID, bool OUT16>
__device__ __forceinline__ void gemm_body(
    uint32_t sb,
    const __nv_bfloat16* __restrict__ A, const __nv_bfloat16* __restrict__ WT,
    const float* __restrict__ bias, const float* __restrict__ resid,
    void* __restrict__ Cv, int K, int M, int row0, int col0, float cscale)
{
    const int tid  = threadIdx.x;
    const int wid  = tid >> 5;           // warpN 0..3
    const int lane = tid & 31;
    const int g = lane >> 2, t = lane & 3;

    const int laneRowA = ((lane >> 3) & 1) * 8 + (lane & 7);
    const int laneKA   = (lane >> 4) * 16;
    const int laneRowB = (lane >> 4) * 8 + (lane & 7);
    const int laneKB   = ((lane >> 3) & 1) * 16;

    float acc[4][4][4];
#pragma unroll
    for (int mt = 0; mt < 4; mt++)
#pragma unroll
        for (int nt = 0; nt < 4; nt++)
#pragma unroll
            for (int f = 0; f < 4; f++) acc[mt][nt][f] = 0.f;

    const int KT = K >> 6;

    auto copy_stage = [&](int kt, int st) {
        const int k0 = kt << 6;
        const uint32_t abase = sb + st * STAGE_BYTES;
        const uint32_t bbase = abase + SA_BYTES;
#pragma unroll
        for (int i = 0; i < 4; i++) {
            int c = tid + (i << 7);                // [0,512)
            int r = c >> 3, sgm = c & 7;
            cp_async16(abase + r * STRD2 + (sgm << 4),
                       &A[(size_t)(row0 + r) * K + k0 + (sgm << 3)]);
        }
#pragma unroll
        for (int i = 0; i < 8; i++) {
            int c = tid + (i << 7);                // [0,1024)
            int n = c >> 3, sgm = c & 7;
            cp_async16(bbase + n * STRD2 + (sgm << 4),
                       &WT[(size_t)(col0 + n) * K + k0 + (sgm << 3)]);
        }
    };

    copy_stage(0, 0);
    cp_commit();

    for (int kt = 0; kt < KT; kt++) {
        const int st = kt & 1;
        cp_wait<0>();          // stage kt resident (only outstanding group)
        __syncthreads();       // all warps done reading the buffer written next
        if (kt + 1 < KT) {
            copy_stage(kt + 1, st ^ 1);
            cp_commit();
        }

        const uint32_t aB = sb + st * STAGE_BYTES + laneRowA * STRD2 + laneKA;
        const uint32_t bB = sb + st * STAGE_BYTES + SA_BYTES
                          + (wid * 32 + laneRowB) * STRD2 + laneKB;
#pragma unroll
        for (int kc = 0; kc < 4; kc++) {
            uint32_t a_[4][4], b_[4][2];
#pragma unroll
            for (int mt = 0; mt < 4; mt++)
                ldsm_x4(a_[mt][0], a_[mt][1], a_[mt][2], a_[mt][3],
                        aB + mt * 16 * STRD2 + (kc << 5));
#pragma unroll
            for (int p = 0; p < 2; p++)
                ldsm_x4(b_[2 * p][0], b_[2 * p][1], b_[2 * p + 1][0], b_[2 * p + 1][1],
                        bB + p * 16 * STRD2 + (kc << 5));
#pragma unroll
            for (int mt = 0; mt < 4; mt++)
#pragma unroll
                for (int nt = 0; nt < 4; nt++)
                    mma_bf16(acc[mt][nt], a_[mt], b_[nt]);
        }
    }

    float* Cf = (float*)Cv;
    __nv_bfloat16* Ch = (__nv_bfloat16*)Cv;
#pragma unroll
    for (int mt = 0; mt < 4; mt++) {
        int r_lo = row0 + mt * 16 + g;
        int r_hi = r_lo + 8;
#pragma unroll
        for (int nt = 0; nt < 4; nt++) {
            int col = col0 + wid * 32 + nt * 8 + (t << 1);
            float2 v0 = make_float2(acc[mt][nt][0] * cscale, acc[mt][nt][1] * cscale);
            float2 v1 = make_float2(acc[mt][nt][2] * cscale, acc[mt][nt][3] * cscale);
            if (BIAS) {
                float2 bv = *(const float2*)&bias[col];
                v0.x += bv.x; v0.y += bv.y;
                v1.x += bv.x; v1.y += bv.y;
            }
            if (RESID) {
                float2 q0 = *(const float2*)&resid[(size_t)r_lo * M + col];
                float2 q1 = *(const float2*)&resid[(size_t)r_hi * M + col];
                v0.x += q0.x; v0.y += q0.y;
                v1.x += q1.x; v1.y += q1.y;
            }
            if (RELU) {
                v0.x = fmaxf(v0.x, 0.f); v0.y = fmaxf(v0.y, 0.f);
                v1.x = fmaxf(v1.x, 0.f); v1.y = fmaxf(v1.y, 0.f);
            }
            if (OUT16) {
                *(__nv_bfloat162*)&Ch[(size_t)r_lo * M + col] =
                    __floats2bfloat162_rn(v0.x, v0.y);
                *(__nv_bfloat162*)&Ch[(size_t)r_hi * M + col] =
                    __floats2bfloat162_rn(v1.x, v1.y);
            } else {
                *(float2*)&Cf[(size_t)r_lo * M + col] = v0;
                *(float2*)&Cf[(size_t)r_hi * M + col] = v1;
            }
        }
    }
}

template<bool RELU, bool BIAS, bool RESID, bool OUT16>
__global__ void __launch_bounds__(128, 4)
bf16_gemm_kernel(const __nv_bfloat16* __restrict__ A,
                 const __nv_bfloat16* __restrict__ WT,
                 const float* __restrict__ bias, const float* __restrict__ resid,
                 void* __restrict__ C, int K, int M)
{
    extern __shared__ char smem[];
    gemm_body<RELU, BIAS, RESID, OUT16>(smem_u32(smem), A, WT, bias, resid, C,
                                        K, M, blockIdx.x * 64, blockIdx.y * 128,
                                        1.0f);
}

// Fused QKV; Q pre-scaled by (1/sqrt(HDIM)) * log2(e) for exp2-domain softmax.
#define QSCALE (0.125f * 1.4426950408889634f)
__global__ void __launch_bounds__(128, 4)
qkv_gemm_kernel(const __nv_bfloat16* __restrict__ A,
                const __nv_bfloat16* __restrict__ wqT,
                const __nv_bfloat16* __restrict__ wkT,
                const __nv_bfloat16* __restrict__ wvT,
                float* __restrict__ q, float* __restrict__ k, float* __restrict__ v)
{
    extern __shared__ char smem[];
    int y = blockIdx.y;
    int sel = y / 3;
    int col0 = (y - sel * 3) * 128;
    const __nv_bfloat16* WT = (sel == 0) ? wqT : (sel == 1) ? wkT : wvT;
    float* C = (sel == 0) ? q : (sel == 1) ? k : v;
    float cscale = (sel == 0) ? QSCALE : 1.0f;
    gemm_body<false, false, false, false>(smem_u32(smem), A, WT, nullptr, nullptr,
                                          C, DIM, DIM, blockIdx.x * 64, col0,
                                          cscale);
}

// ======== merged prologue: weight transpose (blocks 0..1727) + LN1 ============
__global__ void prologue_kernel(
    const float* __restrict__ x, const float* __restrict__ g1,
    const float* __restrict__ be1, __nv_bfloat16* __restrict__ hb,
    const float* __restrict__ wq, const float* __restrict__ wk,
    const float* __restrict__ wv, const float* __restrict__ wo,
    const float* __restrict__ w1, const float* __restrict__ w2,
    __nv_bfloat16* __restrict__ wqT, __nv_bfloat16* __restrict__ wkT,
    __nv_bfloat16* __restrict__ wvT, __nv_bfloat16* __restrict__ woT,
    __nv_bfloat16* __restrict__ w1T, __nv_bfloat16* __restrict__ w2T)
{
    if (blockIdx.x < 1728) {
        __shared__ float tbuf[32][33];
        int id = blockIdx.x;
        int tx = threadIdx.x & 31, ty = threadIdx.x >> 5;  // (32,8)
        const float* in; __nv_bfloat16* out; int R, C, bx, by;
        if (id < 576) {
            int m = id / 144, r = id - m * 144;
            switch (m) {
                case 0: in = wq; out = wqT; break;
                case 1: in = wk; out = wkT; break;
                case 2: in = wv; out = wvT; break;
                default: in = wo; out = woT; break;
            }
            R = DIM; C = DIM; bx = (r % 12) * 32; by = (r / 12) * 32;
        } else if (id < 1152) {
            int r = id - 576;
            in = w1; out = w1T; R = DIM; C = FFDIM;
            bx = (r % 48) * 32; by = (r / 48) * 32;
        } else {
            int r = id - 1152;
            in = w2; out = w2T; R = FFDIM; C = DIM;
            bx = (r % 12) * 32; by = (r / 12) * 32;
        }
#pragma unroll
        for (int i = 0; i < 32; i += 8)
            tbuf[ty + i][tx] = in[(size_t)(by + ty + i) * C + bx + tx];
        __syncthreads();
#pragma unroll
        for (int i = 0; i < 32; i += 8)
            out[(size_t)(bx + ty + i) * R + by + tx] =
                __float2bfloat16_rn(tbuf[tx][ty + i]);
    } else {
        int warp = ((blockIdx.x - 1728) * blockDim.x + threadIdx.x) >> 5;
        int lane = threadIdx.x & 31;
        if (warp >= NTOK) return;
        const float4* row = (const float4*)(x + (size_t)warp * DIM);
        float4 v[3];
        float s = 0.f, ss = 0.f;
#pragma unroll
        for (int i = 0; i < 3; i++) {
            v[i] = row[lane + 32 * i];
            s  += v[i].x + v[i].y + v[i].z + v[i].w;
            ss += v[i].x * v[i].x + v[i].y * v[i].y + v[i].z * v[i].z + v[i].w * v[i].w;
        }
#pragma unroll
        for (int o = 16; o; o >>= 1) {
            s  += __shfl_xor_sync(0xffffffffu, s, o);
            ss += __shfl_xor_sync(0xffffffffu, ss, o);
        }
        float mean = s * (1.0f / DIM);
        float var  = ss * (1.0f / DIM) - mean * mean;
        float rstd = rsqrtf(var + 1e-5f);
        __nv_bfloat16* orow = hb + (size_t)warp * DIM;
#pragma unroll
        for (int i = 0; i < 3; i++) {
            int c4 = lane + 32 * i;
            float4 gv = *(const float4*)&g1[c4 * 4];
            float4 bv = *(const float4*)&be1[c4 * 4];
            float ox = (v[i].x - mean) * rstd * gv.x + bv.x;
            float oy = (v[i].y - mean) * rstd * gv.y + bv.y;
            float oz = (v[i].z - mean) * rstd * gv.z + bv.z;
            float ow = (v[i].w - mean) * rstd * gv.w + bv.w;
            *(__nv_bfloat162*)&orow[c4 * 4]     = __floats2bfloat162_rn(ox, oy);
            *(__nv_bfloat162*)&orow[c4 * 4 + 2] = __floats2bfloat162_rn(oz, ow);
        }
    }
}

// ---------------- LayerNorm (LN2 only) ----------------------------------------
__global__ void ln_kernel(const float* __restrict__ x,
                          const float* __restrict__ g,
                          const float* __restrict__ be,
                          __nv_bfloat16* __restrict__ out)
{
    int warp = (blockIdx.x * blockDim.x + threadIdx.x) >> 5;
    int lane = threadIdx.x & 31;
    if (warp >= NTOK) return;
    const float4* row = (const float4*)(x + (size_t)warp * DIM);
    float4 v[3];
    float s = 0.f, ss = 0.f;
#pragma unroll
    for (int i = 0; i < 3; i++) {
        v[i] = row[lane + 32 * i];
        s  += v[i].x + v[i].y + v[i].z + v[i].w;
        ss += v[i].x * v[i].x + v[i].y * v[i].y + v[i].z * v[i].z + v[i].w * v[i].w;
    }
#pragma unroll
    for (int o = 16; o; o >>= 1) {
        s  += __shfl_xor_sync(0xffffffffu, s, o);
        ss += __shfl_xor_sync(0xffffffffu, ss, o);
    }
    float mean = s * (1.0f / DIM);
    float var  = ss * (1.0f / DIM) - mean * mean;
    float rstd = rsqrtf(var + 1e-5f);
    __nv_bfloat16* orow = out + (size_t)warp * DIM;
#pragma unroll
    for (int i = 0; i < 3; i++) {
        int c4 = lane + 32 * i;
        float4 gv = *(const float4*)&g[c4 * 4];
        float4 bv = *(const float4*)&be[c4 * 4];
        float ox = (v[i].x - mean) * rstd * gv.x + bv.x;
        float oy = (v[i].y - mean) * rstd * gv.y + bv.y;
        float oz = (v[i].z - mean) * rstd * gv.z + bv.z;
        float ow = (v[i].w - mean) * rstd * gv.w + bv.w;
        *(__nv_bfloat162*)&orow[c4 * 4]     = __floats2bfloat162_rn(ox, oy);
        *(__nv_bfloat162*)&orow[c4 * 4 + 2] = __floats2bfloat162_rn(oz, ow);
    }
}

// ---------------- Tensor-core causal flash attention (tf32, bf16 out) ---------
// exp2-domain softmax (Q pre-scaled by 0.125*log2e). Heavy qt tiles first.
#define AT_RS    68
#define AT_RB    (AT_RS * 4)               // 272
#define AT_VRB   (72 * 4)                  // 288
#define AT_KTILE (64 * AT_RB)              // 17408
#define AT_VTILE (64 * AT_VRB)             // 18432
#define AT_STAGE (AT_KTILE + AT_VTILE)     // 35840
#define ATTN_SMEM (2 * AT_STAGE)           // 71680

__global__ void __launch_bounds__(128, 3)
attn_mma_kernel(const float* __restrict__ q, const float* __restrict__ k,
                const float* __restrict__ v, __nv_bfloat16* __restrict__ ctx)
{
    extern __shared__ float sm[];
    const uint32_t sb = smem_u32(sm);

    const int qt = (SEQ / 64 - 1) - blockIdx.x;   // heaviest CTAs launch first
    const int h  = blockIdx.y;
    const int b  = blockIdx.z;
    const int tid = threadIdx.x;
    const int wid = tid >> 5;
    const int lane = tid & 31;
    const int g = lane >> 2, t = lane & 3;
    const int w16 = wid * 16;

    const int laneRowA = ((lane >> 3) & 1) * 8 + (lane & 7);
    const int laneKA   = (lane >> 4) * 16;
    const int laneRowB = (lane >> 4) * 8 + (lane & 7);
    const int laneKB   = ((lane >> 3) & 1) * 16;

    const float* qbase = q + (size_t)b * SEQ * DIM + h * HDIM;
    const float* kbase = k + (size_t)b * SEQ * DIM + h * HDIM;
    const float* vbase = v + (size_t)b * SEQ * DIM + h * HDIM;

    auto stage_off = [&](int st) -> uint32_t {
        return st ? 0u : (uint32_t)AT_STAGE;
    };

#pragma unroll
    for (int i = 0; i < 8; i++) {
        int f = tid + (i << 7);
        int r = f >> 4, d4 = (f & 15) << 2;
        cp_async16(sb + r * AT_RB + (d4 << 2),
                   &qbase[(size_t)(qt * 64 + r) * DIM + d4]);
    }
    auto copy_kv = [&](int kt, int st) {
        const uint32_t kdst = sb + stage_off(st);
        const uint32_t vdst = kdst + AT_KTILE;
#pragma unroll
        for (int i = 0; i < 8; i++) {
            int f = tid + (i << 7);
            int r = f >> 4, d4 = (f & 15) << 2;
            cp_async16(kdst + r * AT_RB + (d4 << 2),
                       &kbase[(size_t)(kt * 64 + r) * DIM + d4]);
        }
#pragma unroll
        for (int i = 0; i < 8; i++) {
            int f = tid + (i << 7);
            int r = f >> 4, d4 = (f & 15) << 2;
            cp_async16(vdst + r * AT_VRB + (d4 << 2),
                       &vbase[(size_t)(kt * 64 + r) * DIM + d4]);
        }
    };

    copy_kv(0, 0);
    cp_commit();
    cp_wait<0>();
    __syncthreads();

    uint32_t qfrag[8][4];
    {
        const uint32_t aQ = sb + (w16 + laneRowA) * AT_RB + laneKA;
#pragma unroll
        for (int kc = 0; kc < 8; kc++)
            ldsm_x4(qfrag[kc][0], qfrag[kc][1], qfrag[kc][2], qfrag[kc][3],
                    aQ + (kc << 5));
    }
    __syncthreads();

    float m0 = -1e30f, m1 = -1e30f, l0 = 0.f, l1 = 0.f;
    float accO[8][4];
#pragma unroll
    for (int nt = 0; nt < 8; nt++)
#pragma unroll
        for (int f = 0; f < 4; f++) accO[nt][f] = 0.f;

    const int r0loc = w16 + g;
    const int src_lo = (lane & ~3) | (t >> 1);
    const int src_hi = src_lo + 2;

    const int KT = qt + 1;
    for (int kt = 0; kt < KT; kt++) {
        const int st = kt & 1;
        if (kt > 0) {
            cp_wait<0>();
            __syncthreads();
        }
        if (kt + 1 < KT) {
            copy_kv(kt + 1, st ^ 1);
            cp_commit();
        }

        float accS[8][4];
#pragma unroll
        for (int nt = 0; nt < 8; nt++)
#pragma unroll
            for (int f = 0; f < 4; f++) accS[nt][f] = 0.f;

        const uint32_t bK = sb + stage_off(st) + laneRowB * AT_RB + laneKB;
#pragma unroll
        for (int kc = 0; kc < 8; kc++) {
            uint32_t b_[8][2];
#pragma unroll
            for (int p = 0; p < 4; p++)
                ldsm_x4(b_[2 * p][0], b_[2 * p][1], b_[2 * p + 1][0], b_[2 * p + 1][1],
                        bK + p * 16 * AT_RB + (kc << 5));
#pragma unroll
            for (int nt = 0; nt < 8; nt++)
                mma_tf32(accS[nt], qfrag[kc], b_[nt]);
        }

        if (kt == qt) {
#pragma unroll
            for (int nt = 0; nt < 8; nt++) {
                int c = nt * 8 + (t << 1);
                accS[nt][0] = (c     > r0loc)     ? -1e30f : accS[nt][0];
                accS[nt][1] = (c + 1 > r0loc)     ? -1e30f : accS[nt][1];
                accS[nt][2] = (c     > r0loc + 8) ? -1e30f : accS[nt][2];
                accS[nt][3] = (c + 1 > r0loc + 8) ? -1e30f : accS[nt][3];
            }
        }

        float pm0 = -1e30f, pm1 = -1e30f;
#pragma unroll
        for (int nt = 0; nt < 8; nt++) {
            pm0 = fmaxf(pm0, fmaxf(accS[nt][0], accS[nt][1]));
            pm1 = fmaxf(pm1, fmaxf(accS[nt][2], accS[nt][3]));
        }
        pm0 = fmaxf(pm0, __shfl_xor_sync(0xffffffffu, pm0, 1));
        pm0 = fmaxf(pm0, __shfl_xor_sync(0xffffffffu, pm0, 2));
        pm1 = fmaxf(pm1, __shfl_xor_sync(0xffffffffu, pm1, 1));
        pm1 = fmaxf(pm1, __shfl_xor_sync(0xffffffffu, pm1, 2));
        float mn0 = fmaxf(m0, pm0), mn1 = fmaxf(m1, pm1);
        float al0 = ex2f(m0 - mn0), al1 = ex2f(m1 - mn1);
        m0 = mn0; m1 = mn1;
        float sum0 = 0.f, sum1 = 0.f;
#pragma unroll
        for (int nt = 0; nt < 8; nt++) {
            accS[nt][0] = ex2f(accS[nt][0] - mn0);
            accS[nt][1] = ex2f(accS[nt][1] - mn0);
            accS[nt][2] = ex2f(accS[nt][2] - mn1);
            accS[nt][3] = ex2f(accS[nt][3] - mn1);
            sum0 += accS[nt][0] + accS[nt][1];
            sum1 += accS[nt][2] + accS[nt][3];
        }
        sum0 += __shfl_xor_sync(0xffffffffu, sum0, 1);
        sum0 += __shfl_xor_sync(0xffffffffu, sum0, 2);
        sum1 += __shfl_xor_sync(0xffffffffu, sum1, 1);
        sum1 += __shfl_xor_sync(0xffffffffu, sum1, 2);
        l0 = l0 * al0 + sum0;
        l1 = l1 * al1 + sum1;

#pragma unroll
        for (int nt = 0; nt < 8; nt++) {
            accO[nt][0] *= al0; accO[nt][1] *= al0;
            accO[nt][2] *= al1; accO[nt][3] *= al1;
        }
        const uint32_t bV = sb + stage_off(st) + AT_KTILE
                          + t * AT_VRB + (g << 2);
#pragma unroll
        for (int kc = 0; kc < 8; kc++) {
            float x0 = __shfl_sync(0xffffffffu, accS[kc][0], src_lo);
            float x1 = __shfl_sync(0xffffffffu, accS[kc][1], src_lo);
            float y0 = __shfl_sync(0xffffffffu, accS[kc][0], src_hi);
            float y1 = __shfl_sync(0xffffffffu, accS[kc][1], src_hi);
            float z0 = __shfl_sync(0xffffffffu, accS[kc][2], src_lo);
            float z1 = __shfl_sync(0xffffffffu, accS[kc][3], src_lo);
            float u0 = __shfl_sync(0xffffffffu, accS[kc][2], src_hi);
            float u1 = __shfl_sync(0xffffffffu, accS[kc][3], src_hi);
            uint32_t a_[4];
            a_[0] = __float_as_uint((t & 1) ? x1 : x0);
            a_[1] = __float_as_uint((t & 1) ? z1 : z0);
            a_[2] = __float_as_uint((t & 1) ? y1 : y0);
            a_[3] = __float_as_uint((t & 1) ? u1 : u0);
#pragma unroll
            for (int nt = 0; nt < 8; nt++) {
                uint32_t b_[2];
                uint32_t ba = bV + kc * 8 * AT_VRB + (nt << 5);
                b_[0] = lds32(ba);
                b_[1] = lds32(ba + 4 * AT_VRB);
                mma_tf32(accO[nt], a_, b_);
            }
        }
    }

    {
        const int r0 = w16 + g, r1 = r0 + 8;
        float inv0 = 1.0f / l0;
        float inv1 = 1.0f / l1;
        __nv_bfloat16* obase = ctx + (size_t)b * SEQ * DIM + h * HDIM;
        __nv_bfloat16* o0 = &obase[(size_t)(qt * 64 + r0) * DIM];
        __nv_bfloat16* o1 = &obase[(size_t)(qt * 64 + r1) * DIM];
#pragma unroll
        for (int nt = 0; nt < 8; nt++) {
            int c = nt * 8 + (t << 1);
            *(__nv_bfloat162*)&o0[c] =
                __floats2bfloat162_rn(accO[nt][0] * inv0, accO[nt][1] * inv0);
            *(__nv_bfloat162*)&o1[c] =
                __floats2bfloat162_rn(accO[nt][2] * inv1, accO[nt][3] * inv1);
        }
    }
}

// ---------------- launch ------------------------------------------------------
template<typename T>
static T* dev_ptr_t(const void* sym)
{
    void* p = nullptr;
    cudaGetSymbolAddress(&p, sym);
    return (T*)p;
}

extern "C" void kernel_launch(void* const* d_in, const int* in_sizes, int n_in,
                              void* d_out, int out_size)
{
    (void)in_sizes; (void)n_in; (void)out_size;
    const float* x   = (const float*)d_in[0];
    const float* wq  = (const float*)d_in[1];
    const float* wk  = (const float*)d_in[2];
    const float* wv  = (const float*)d_in[3];
    const float* wo  = (const float*)d_in[4];
    const float* bo  = (const float*)d_in[5];
    const float* w1  = (const float*)d_in[6];
    const float* b1  = (const float*)d_in[7];
    const float* w2  = (const float*)d_in[8];
    const float* b2  = (const float*)d_in[9];
    const float* g1  = (const float*)d_in[10];
    const float* be1 = (const float*)d_in[11];
    const float* g2  = (const float*)d_in[12];
    const float* be2 = (const float*)d_in[13];
    float* out = (float*)d_out;

    __nv_bfloat16* hb  = dev_ptr_t<__nv_bfloat16>(g_hb);
    float* qb          = dev_ptr_t<float>(g_q);
    float* kb          = dev_ptr_t<float>(g_k);
    float* vb          = dev_ptr_t<float>(g_v);
    __nv_bfloat16* ctxb = dev_ptr_t<__nv_bfloat16>(g_ctxb);
    float* x1          = dev_ptr_t<float>(g_x1);
    __nv_bfloat16* ffb = dev_ptr_t<__nv_bfloat16>(g_ffb);
    __nv_bfloat16* wqT = dev_ptr_t<__nv_bfloat16>(g_wqT);
    __nv_bfloat16* wkT = dev_ptr_t<__nv_bfloat16>(g_wkT);
    __nv_bfloat16* wvT = dev_ptr_t<__nv_bfloat16>(g_wvT);
    __nv_bfloat16* woT = dev_ptr_t<__nv_bfloat16>(g_woT);
    __nv_bfloat16* w1T = dev_ptr_t<__nv_bfloat16>(g_w1T);
    __nv_bfloat16* w2T = dev_ptr_t<__nv_bfloat16>(g_w2T);

    cudaFuncSetAttribute(attn_mma_kernel, cudaFuncAttributeMaxDynamicSharedMemorySize, ATTN_SMEM);
    cudaFuncSetAttribute(qkv_gemm_kernel,
                         cudaFuncAttributeMaxDynamicSharedMemorySize, GEMM_SMEM);
    cudaFuncSetAttribute(bf16_gemm_kernel<false, true, true, false>,
                         cudaFuncAttributeMaxDynamicSharedMemorySize, GEMM_SMEM);
    cudaFuncSetAttribute(bf16_gemm_kernel<true, true, false, true>,
                         cudaFuncAttributeMaxDynamicSharedMemorySize, GEMM_SMEM);

    // prologue: weight transposes + LN1 in one launch
    prologue_kernel<<<1728 + NTOK / 8, 256>>>(x, g1, be1, hb,
                                              wq, wk, wv, wo, w1, w2,
                                              wqT, wkT, wvT, woT, w1T, w2T);
    // fused QKV projections (64-row tiles, 4 CTAs/SM)
    qkv_gemm_kernel<<<dim3(NTOK / 64, 9), 128, GEMM_SMEM>>>(hb, wqT, wkT, wvT, qb, kb, vb);
    // attention
    attn_mma_kernel<<<dim3(SEQ / 64, NHEAD, BATCH), 128, ATTN_SMEM>>>(qb, kb, vb, ctxb);
    // output projection + residual
    bf16_gemm_kernel<false, true, true, false><<<dim3(NTOK / 64, 3), 128, GEMM_SMEM>>>(
        ctxb, woT, bo, x, x1, DIM, DIM);
    // LN2
    ln_kernel<<<NTOK / 8, 256>>>(x1, g2, be2, hb);
    // FFN1 (ReLU, bf16 out)
    bf16_gemm_kernel<true, true, false, true><<<dim3(NTOK / 64, 12), 128, GEMM_SMEM>>>(
        hb, w1T, b1, nullptr, ffb, DIM, FFDIM);
    // FFN2 (+residual)
    bf16_gemm_kernel<false, true, true, false><<<dim3(NTOK / 64, 3), 128, GEMM_SMEM>>>(
        ffb, w2T, b2, x1, out, FFDIM, DIM);
}

// round 17
// speedup vs baseline: 1.0835x; 1.0178x over previous
#include <cuda_runtime.h>
#include <cuda_bf16.h>
#include <cstdint>
#include <math.h>

// Problem dims
#define BATCH 64
#define SEQ   256
#define DIM   384
#define NHEAD 6
#define HDIM  64
#define NTOK  (BATCH * SEQ)      // 16384
#define FFDIM (4 * DIM)          // 1536

// ---------------- scratch (static device globals; no allocation) -------------
__device__ __nv_bfloat16 g_hb [NTOK * DIM];
__device__ float         g_q  [NTOK * DIM];
__device__ float         g_k  [NTOK * DIM];
__device__ float         g_v  [NTOK * DIM];
__device__ __nv_bfloat16 g_ctxb[NTOK * DIM];
__device__ float         g_x1 [NTOK * DIM];
__device__ __nv_bfloat16 g_ffb[NTOK * FFDIM];
__device__ __nv_bfloat16 g_wqT[DIM * DIM];
__device__ __nv_bfloat16 g_wkT[DIM * DIM];
__device__ __nv_bfloat16 g_wvT[DIM * DIM];
__device__ __nv_bfloat16 g_woT[DIM * DIM];
__device__ __nv_bfloat16 g_w1T[DIM * FFDIM];
__device__ __nv_bfloat16 g_w2T[FFDIM * DIM];

// ---------------- PTX helpers -------------------------------------------------
__device__ __forceinline__ uint32_t smem_u32(const void* p) {
    uint32_t a;
    asm("{ .reg .u64 t; cvta.to.shared.u64 t, %1; cvt.u32.u64 %0, t; }"
        : "=r"(a) : "l"(p));
    return a;
}
__device__ __forceinline__ void cp_async16(uint32_t dst, const void* src) {
    asm volatile("cp.async.cg.shared.global [%0], [%1], 16;" :: "r"(dst), "l"(src));
}
__device__ __forceinline__ void cp_async16_ca(uint32_t dst, const void* src) {
    asm volatile("cp.async.ca.shared.global [%0], [%1], 16;" :: "r"(dst), "l"(src));
}
__device__ __forceinline__ void cp_commit() {
    asm volatile("cp.async.commit_group;" ::: "memory");
}
template<int N> __device__ __forceinline__ void cp_wait() {
    asm volatile("cp.async.wait_group %0;" :: "n"(N) : "memory");
}
__device__ __forceinline__ void mma_tf32(float* c, const uint32_t* a, const uint32_t* b) {
    asm volatile(
        "mma.sync.aligned.m16n8k8.row.col.f32.tf32.tf32.f32 "
        "{%0,%1,%2,%3}, {%4,%5,%6,%7}, {%8,%9}, {%0,%1,%2,%3};"
        : "+f"(c[0]), "+f"(c[1]), "+f"(c[2]), "+f"(c[3])
        : "r"(a[0]), "r"(a[1]), "r"(a[2]), "r"(a[3]), "r"(b[0]), "r"(b[1]));
}
__device__ __forceinline__ void mma_bf16(float* c, const uint32_t* a, const uint32_t* b) {
    asm volatile(
        "mma.sync.aligned.m16n8k16.row.col.f32.bf16.bf16.f32 "
        "{%0,%1,%2,%3}, {%4,%5,%6,%7}, {%8,%9}, {%0,%1,%2,%3};"
        : "+f"(c[0]), "+f"(c[1]), "+f"(c[2]), "+f"(c[3])
        : "r"(a[0]), "r"(a[1]), "r"(a[2]), "r"(a[3]), "r"(b[0]), "r"(b[1]));
}
__device__ __forceinline__ void ldsm_x4(uint32_t& r0, uint32_t& r1, uint32_t& r2,
                                        uint32_t& r3, uint32_t addr) {
    asm volatile("ldmatrix.sync.aligned.m8n8.x4.shared.b16 {%0,%1,%2,%3}, [%4];"
                 : "=r"(r0), "=r"(r1), "=r"(r2), "=r"(r3) : "r"(addr));
}
__device__ __forceinline__ uint32_t lds32(uint32_t addr) {
    uint32_t v;
    asm volatile("ld.shared.b32 %0, [%1];" : "=r"(v) : "r"(addr));
    return v;
}
__device__ __forceinline__ float ex2f(float x) {
    float y;
    asm("ex2.approx.f32 %0, %1;" : "=f"(y) : "f"(x));
    return y;
}

// ====== bf16 mma.sync GEMM, 128x128 tile, BK=64, 2-stage, .ca B loads ========
// A: [N,K] bf16 row-major (streamed, .cg), WT: [M,K] bf16 row-major (shared by
// co-resident CTAs with the same blockIdx.y -> .ca so the 2nd CTA hits L1;
// 2-stage/73.7KB smem keeps ~81KB of L1D carveout alive).
// 256 threads, 8 warps (2x4), warp tile 64x32 (the proven microtile).
#define BK       64
#define STRD2    144                       // bytes per bf16 smem row (64 bf16 + pad)
#define SA_BYTES (128 * STRD2)             // 18432
#define SB_BYTES (128 * STRD2)             // 18432
#define STAGE_BYTES (SA_BYTES + SB_BYTES)  // 36864
#define GEMM_SMEM (2 * STAGE_BYTES)        // 73728

template<bool RELU, bool BIAS, bool RESID, bool OUT16>
__device__ __forceinline__ void gemm_body(
    uint32_t sb,
    const __nv_bfloat16* __restrict__ A, const __nv_bfloat16* __restrict__ WT,
    const float* __restrict__ bias, const float* __restrict__ resid,
    void* __restrict__ Cv, int K, int M, int row0, int col0, float cscale)
{
    const int tid  = threadIdx.x;
    const int wid  = tid >> 5;
    const int lane = tid & 31;
    const int warpM = wid & 1;
    const int warpN = wid >> 1;
    const int g = lane >> 2, t = lane & 3;

    const int laneRowA = ((lane >> 3) & 1) * 8 + (lane & 7);
    const int laneKA   = (lane >> 4) * 16;
    const int laneRowB = (lane >> 4) * 8 + (lane & 7);
    const int laneKB   = ((lane >> 3) & 1) * 16;

    float acc[4][4][4];
#pragma unroll
    for (int mt = 0; mt < 4; mt++)
#pragma unroll
        for (int nt = 0; nt < 4; nt++)
#pragma unroll
            for (int f = 0; f < 4; f++) acc[mt][nt][f] = 0.f;

    const int KT = K >> 6;

    auto copy_stage = [&](int kt, int st) {
        const int k0 = kt << 6;
        const uint32_t abase = sb + st * STAGE_BYTES;
        const uint32_t bbase = abase + SA_BYTES;
#pragma unroll
        for (int i = 0; i < 4; i++) {
            int c = tid + (i << 8);                // [0,1024)
            int r = c >> 3, sgm = c & 7;
            cp_async16(abase + r * STRD2 + (sgm << 4),
                       &A[(size_t)(row0 + r) * K + k0 + (sgm << 3)]);
        }
#pragma unroll
        for (int i = 0; i < 4; i++) {
            int c = tid + (i << 8);
            int n = c >> 3, sgm = c & 7;
            cp_async16_ca(bbase + n * STRD2 + (sgm << 4),
                          &WT[(size_t)(col0 + n) * K + k0 + (sgm << 3)]);
        }
    };

    copy_stage(0, 0);
    cp_commit();

    for (int kt = 0; kt < KT; kt++) {
        const int st = kt & 1;
        cp_wait<0>();
        __syncthreads();
        if (kt + 1 < KT) {
            copy_stage(kt + 1, st ^ 1);
            cp_commit();
        }

        const uint32_t aB = sb + st * STAGE_BYTES
                          + (warpM * 64 + laneRowA) * STRD2 + laneKA;
        const uint32_t bB = sb + st * STAGE_BYTES + SA_BYTES
                          + (warpN * 32 + laneRowB) * STRD2 + laneKB;
#pragma unroll
        for (int kc = 0; kc < 4; kc++) {
            uint32_t a_[4][4], b_[4][2];
#pragma unroll
            for (int mt = 0; mt < 4; mt++)
                ldsm_x4(a_[mt][0], a_[mt][1], a_[mt][2], a_[mt][3],
                        aB + mt * 16 * STRD2 + (kc << 5));
#pragma unroll
            for (int p = 0; p < 2; p++)
                ldsm_x4(b_[2 * p][0], b_[2 * p][1], b_[2 * p + 1][0], b_[2 * p + 1][1],
                        bB + p * 16 * STRD2 + (kc << 5));
#pragma unroll
            for (int mt = 0; mt < 4; mt++)
#pragma unroll
                for (int nt = 0; nt < 4; nt++)
                    mma_bf16(acc[mt][nt], a_[mt], b_[nt]);
        }
    }

    float* Cf = (float*)Cv;
    __nv_bfloat16* Ch = (__nv_bfloat16*)Cv;
#pragma unroll
    for (int mt = 0; mt < 4; mt++) {
        int r_lo = row0 + warpM * 64 + mt * 16 + g;
        int r_hi = r_lo + 8;
#pragma unroll
        for (int nt = 0; nt < 4; nt++) {
            int col = col0 + warpN * 32 + nt * 8 + (t << 1);
            float2 v0 = make_float2(acc[mt][nt][0] * cscale, acc[mt][nt][1] * cscale);
            float2 v1 = make_float2(acc[mt][nt][2] * cscale, acc[mt][nt][3] * cscale);
            if (BIAS) {
                float2 bv = *(const float2*)&bias[col];
                v0.x += bv.x; v0.y += bv.y;
                v1.x += bv.x; v1.y += bv.y;
            }
            if (RESID) {
                float2 q0 = *(const float2*)&resid[(size_t)r_lo * M + col];
                float2 q1 = *(const float2*)&resid[(size_t)r_hi * M + col];
                v0.x += q0.x; v0.y += q0.y;
                v1.x += q1.x; v1.y += q1.y;
            }
            if (RELU) {
                v0.x = fmaxf(v0.x, 0.f); v0.y = fmaxf(v0.y, 0.f);
                v1.x = fmaxf(v1.x, 0.f); v1.y = fmaxf(v1.y, 0.f);
            }
            if (OUT16) {
                *(__nv_bfloat162*)&Ch[(size_t)r_lo * M + col] =
                    __floats2bfloat162_rn(v0.x, v0.y);
                *(__nv_bfloat162*)&Ch[(size_t)r_hi * M + col] =
                    __floats2bfloat162_rn(v1.x, v1.y);
            } else {
                *(float2*)&Cf[(size_t)r_lo * M + col] = v0;
                *(float2*)&Cf[(size_t)r_hi * M + col] = v1;
            }
        }
    }
}

template<bool RELU, bool BIAS, bool RESID, bool OUT16>
__global__ void __launch_bounds__(256, 2)
bf16_gemm_kernel(const __nv_bfloat16* __restrict__ A,
                 const __nv_bfloat16* __restrict__ WT,
                 const float* __restrict__ bias, const float* __restrict__ resid,
                 void* __restrict__ C, int K, int M)
{
    extern __shared__ char smem[];
    gemm_body<RELU, BIAS, RESID, OUT16>(smem_u32(smem), A, WT, bias, resid, C,
                                        K, M, blockIdx.x * 128, blockIdx.y * 128,
                                        1.0f);
}

// Fused QKV; Q pre-scaled by (1/sqrt(HDIM)) * log2(e) for exp2-domain softmax.
#define QSCALE (0.125f * 1.4426950408889634f)
__global__ void __launch_bounds__(256, 2)
qkv_gemm_kernel(const __nv_bfloat16* __restrict__ A,
                const __nv_bfloat16* __restrict__ wqT,
                const __nv_bfloat16* __restrict__ wkT,
                const __nv_bfloat16* __restrict__ wvT,
                float* __restrict__ q, float* __restrict__ k, float* __restrict__ v)
{
    extern __shared__ char smem[];
    int y = blockIdx.y;
    int sel = y / 3;
    int col0 = (y - sel * 3) * 128;
    const __nv_bfloat16* WT = (sel == 0) ? wqT : (sel == 1) ? wkT : wvT;
    float* C = (sel == 0) ? q : (sel == 1) ? k : v;
    float cscale = (sel == 0) ? QSCALE : 1.0f;
    gemm_body<false, false, false, false>(smem_u32(smem), A, WT, nullptr, nullptr,
                                          C, DIM, DIM, blockIdx.x * 128, col0,
                                          cscale);
}

// ======== merged prologue: weight transpose (blocks 0..1727) + LN1 ============
__global__ void prologue_kernel(
    const float* __restrict__ x, const float* __restrict__ g1,
    const float* __restrict__ be1, __nv_bfloat16* __restrict__ hb,
    const float* __restrict__ wq, const float* __restrict__ wk,
    const float* __restrict__ wv, const float* __restrict__ wo,
    const float* __restrict__ w1, const float* __restrict__ w2,
    __nv_bfloat16* __restrict__ wqT, __nv_bfloat16* __restrict__ wkT,
    __nv_bfloat16* __restrict__ wvT, __nv_bfloat16* __restrict__ woT,
    __nv_bfloat16* __restrict__ w1T, __nv_bfloat16* __restrict__ w2T)
{
    if (blockIdx.x < 1728) {
        __shared__ float tbuf[32][33];
        int id = blockIdx.x;
        int tx = threadIdx.x & 31, ty = threadIdx.x >> 5;  // (32,8)
        const float* in; __nv_bfloat16* out; int R, C, bx, by;
        if (id < 576) {
            int m = id / 144, r = id - m * 144;
            switch (m) {
                case 0: in = wq; out = wqT; break;
                case 1: in = wk; out = wkT; break;
                case 2: in = wv; out = wvT; break;
                default: in = wo; out = woT; break;
            }
            R = DIM; C = DIM; bx = (r % 12) * 32; by = (r / 12) * 32;
        } else if (id < 1152) {
            int r = id - 576;
            in = w1; out = w1T; R = DIM; C = FFDIM;
            bx = (r % 48) * 32; by = (r / 48) * 32;
        } else {
            int r = id - 1152;
            in = w2; out = w2T; R = FFDIM; C = DIM;
            bx = (r % 12) * 32; by = (r / 12) * 32;
        }
#pragma unroll
        for (int i = 0; i < 32; i += 8)
            tbuf[ty + i][tx] = in[(size_t)(by + ty + i) * C + bx + tx];
        __syncthreads();
#pragma unroll
        for (int i = 0; i < 32; i += 8)
            out[(size_t)(bx + ty + i) * R + by + tx] =
                __float2bfloat16_rn(tbuf[tx][ty + i]);
    } else {
        int warp = ((blockIdx.x - 1728) * blockDim.x + threadIdx.x) >> 5;
        int lane = threadIdx.x & 31;
        if (warp >= NTOK) return;
        const float4* row = (const float4*)(x + (size_t)warp * DIM);
        float4 v[3];
        float s = 0.f, ss = 0.f;
#pragma unroll
        for (int i = 0; i < 3; i++) {
            v[i] = row[lane + 32 * i];
            s  += v[i].x + v[i].y + v[i].z + v[i].w;
            ss += v[i].x * v[i].x + v[i].y * v[i].y + v[i].z * v[i].z + v[i].w * v[i].w;
        }
#pragma unroll
        for (int o = 16; o; o >>= 1) {
            s  += __shfl_xor_sync(0xffffffffu, s, o);
            ss += __shfl_xor_sync(0xffffffffu, ss, o);
        }
        float mean = s * (1.0f / DIM);
        float var  = ss * (1.0f / DIM) - mean * mean;
        float rstd = rsqrtf(var + 1e-5f);
        __nv_bfloat16* orow = hb + (size_t)warp * DIM;
#pragma unroll
        for (int i = 0; i < 3; i++) {
            int c4 = lane + 32 * i;
            float4 gv = *(const float4*)&g1[c4 * 4];
            float4 bv = *(const float4*)&be1[c4 * 4];
            float ox = (v[i].x - mean) * rstd * gv.x + bv.x;
            float oy = (v[i].y - mean) * rstd * gv.y + bv.y;
            float oz = (v[i].z - mean) * rstd * gv.z + bv.z;
            float ow = (v[i].w - mean) * rstd * gv.w + bv.w;
            *(__nv_bfloat162*)&orow[c4 * 4]     = __floats2bfloat162_rn(ox, oy);
            *(__nv_bfloat162*)&orow[c4 * 4 + 2] = __floats2bfloat162_rn(oz, ow);
        }
    }
}

// ---------------- LayerNorm (LN2 only) ----------------------------------------
__global__ void ln_kernel(const float* __restrict__ x,
                          const float* __restrict__ g,
                          const float* __restrict__ be,
                          __nv_bfloat16* __restrict__ out)
{
    int warp = (blockIdx.x * blockDim.x + threadIdx.x) >> 5;
    int lane = threadIdx.x & 31;
    if (warp >= NTOK) return;
    const float4* row = (const float4*)(x + (size_t)warp * DIM);
    float4 v[3];
    float s = 0.f, ss = 0.f;
#pragma unroll
    for (int i = 0; i < 3; i++) {
        v[i] = row[lane + 32 * i];
        s  += v[i].x + v[i].y + v[i].z + v[i].w;
        ss += v[i].x * v[i].x + v[i].y * v[i].y + v[i].z * v[i].z + v[i].w * v[i].w;
    }
#pragma unroll
    for (int o = 16; o; o >>= 1) {
        s  += __shfl_xor_sync(0xffffffffu, s, o);
        ss += __shfl_xor_sync(0xffffffffu, ss, o);
    }
    float mean = s * (1.0f / DIM);
    float var  = ss * (1.0f / DIM) - mean * mean;
    float rstd = rsqrtf(var + 1e-5f);
    __nv_bfloat16* orow = out + (size_t)warp * DIM;
#pragma unroll
    for (int i = 0; i < 3; i++) {
        int c4 = lane + 32 * i;
        float4 gv = *(const float4*)&g[c4 * 4];
        float4 bv = *(const float4*)&be[c4 * 4];
        float ox = (v[i].x - mean) * rstd * gv.x + bv.x;
        float oy = (v[i].y - mean) * rstd * gv.y + bv.y;
        float oz = (v[i].z - mean) * rstd * gv.z + bv.z;
        float ow = (v[i].w - mean) * rstd * gv.w + bv.w;
        *(__nv_bfloat162*)&orow[c4 * 4]     = __floats2bfloat162_rn(ox, oy);
        *(__nv_bfloat162*)&orow[c4 * 4 + 2] = __floats2bfloat162_rn(oz, ow);
    }
}

// ---------------- Tensor-core causal flash attention (tf32, bf16 out) ---------
// exp2-domain softmax (Q pre-scaled by 0.125*log2e). Heavy qt tiles first.
#define AT_RS    68
#define AT_RB    (AT_RS * 4)               // 272
#define AT_VRB   (72 * 4)                  // 288
#define AT_KTILE (64 * AT_RB)              // 17408
#define AT_VTILE (64 * AT_VRB)             // 18432
#define AT_STAGE (AT_KTILE + AT_VTILE)     // 35840
#define ATTN_SMEM (2 * AT_STAGE)           // 71680

__global__ void __launch_bounds__(128, 3)
attn_mma_kernel(const float* __restrict__ q, const float* __restrict__ k,
                const float* __restrict__ v, __nv_bfloat16* __restrict__ ctx)
{
    extern __shared__ float sm[];
    const uint32_t sb = smem_u32(sm);

    const int qt = (SEQ / 64 - 1) - blockIdx.x;   // heaviest CTAs launch first
    const int h  = blockIdx.y;
    const int b  = blockIdx.z;
    const int tid = threadIdx.x;
    const int wid = tid >> 5;
    const int lane = tid & 31;
    const int g = lane >> 2, t = lane & 3;
    const int w16 = wid * 16;

    const int laneRowA = ((lane >> 3) & 1) * 8 + (lane & 7);
    const int laneKA   = (lane >> 4) * 16;
    const int laneRowB = (lane >> 4) * 8 + (lane & 7);
    const int laneKB   = ((lane >> 3) & 1) * 16;

    const float* qbase = q + (size_t)b * SEQ * DIM + h * HDIM;
    const float* kbase = k + (size_t)b * SEQ * DIM + h * HDIM;
    const float* vbase = v + (size_t)b * SEQ * DIM + h * HDIM;

    auto stage_off = [&](int st) -> uint32_t {
        return st ? 0u : (uint32_t)AT_STAGE;
    };

#pragma unroll
    for (int i = 0; i < 8; i++) {
        int f = tid + (i << 7);
        int r = f >> 4, d4 = (f & 15) << 2;
        cp_async16(sb + r * AT_RB + (d4 << 2),
                   &qbase[(size_t)(qt * 64 + r) * DIM + d4]);
    }
    auto copy_kv = [&](int kt, int st) {
        const uint32_t kdst = sb + stage_off(st);
        const uint32_t vdst = kdst + AT_KTILE;
#pragma unroll
        for (int i = 0; i < 8; i++) {
            int f = tid + (i << 7);
            int r = f >> 4, d4 = (f & 15) << 2;
            cp_async16(kdst + r * AT_RB + (d4 << 2),
                       &kbase[(size_t)(kt * 64 + r) * DIM + d4]);
        }
#pragma unroll
        for (int i = 0; i < 8; i++) {
            int f = tid + (i << 7);
            int r = f >> 4, d4 = (f & 15) << 2;
            cp_async16(vdst + r * AT_VRB + (d4 << 2),
                       &vbase[(size_t)(kt * 64 + r) * DIM + d4]);
        }
    };

    copy_kv(0, 0);
    cp_commit();
    cp_wait<0>();
    __syncthreads();

    uint32_t qfrag[8][4];
    {
        const uint32_t aQ = sb + (w16 + laneRowA) * AT_RB + laneKA;
#pragma unroll
        for (int kc = 0; kc < 8; kc++)
            ldsm_x4(qfrag[kc][0], qfrag[kc][1], qfrag[kc][2], qfrag[kc][3],
                    aQ + (kc << 5));
    }
    __syncthreads();

    float m0 = -1e30f, m1 = -1e30f, l0 = 0.f, l1 = 0.f;
    float accO[8][4];
#pragma unroll
    for (int nt = 0; nt < 8; nt++)
#pragma unroll
        for (int f = 0; f < 4; f++) accO[nt][f] = 0.f;

    const int r0loc = w16 + g;
    const int src_lo = (lane & ~3) | (t >> 1);
    const int src_hi = src_lo + 2;

    const int KT = qt + 1;
    for (int kt = 0; kt < KT; kt++) {
        const int st = kt & 1;
        if (kt > 0) {
            cp_wait<0>();
            __syncthreads();
        }
        if (kt + 1 < KT) {
            copy_kv(kt + 1, st ^ 1);
            cp_commit();
        }

        float accS[8][4];
#pragma unroll
        for (int nt = 0; nt < 8; nt++)
#pragma unroll
            for (int f = 0; f < 4; f++) accS[nt][f] = 0.f;

        const uint32_t bK = sb + stage_off(st) + laneRowB * AT_RB + laneKB;
#pragma unroll
        for (int kc = 0; kc < 8; kc++) {
            uint32_t b_[8][2];
#pragma unroll
            for (int p = 0; p < 4; p++)
                ldsm_x4(b_[2 * p][0], b_[2 * p][1], b_[2 * p + 1][0], b_[2 * p + 1][1],
                        bK + p * 16 * AT_RB + (kc << 5));
#pragma unroll
            for (int nt = 0; nt < 8; nt++)
                mma_tf32(accS[nt], qfrag[kc], b_[nt]);
        }

        if (kt == qt) {
#pragma unroll
            for (int nt = 0; nt < 8; nt++) {
                int c = nt * 8 + (t << 1);
                accS[nt][0] = (c     > r0loc)     ? -1e30f : accS[nt][0];
                accS[nt][1] = (c + 1 > r0loc)     ? -1e30f : accS[nt][1];
                accS[nt][2] = (c     > r0loc + 8) ? -1e30f : accS[nt][2];
                accS[nt][3] = (c + 1 > r0loc + 8) ? -1e30f : accS[nt][3];
            }
        }

        float pm0 = -1e30f, pm1 = -1e30f;
#pragma unroll
        for (int nt = 0; nt < 8; nt++) {
            pm0 = fmaxf(pm0, fmaxf(accS[nt][0], accS[nt][1]));
            pm1 = fmaxf(pm1, fmaxf(accS[nt][2], accS[nt][3]));
        }
        pm0 = fmaxf(pm0, __shfl_xor_sync(0xffffffffu, pm0, 1));
        pm0 = fmaxf(pm0, __shfl_xor_sync(0xffffffffu, pm0, 2));
        pm1 = fmaxf(pm1, __shfl_xor_sync(0xffffffffu, pm1, 1));
        pm1 = fmaxf(pm1, __shfl_xor_sync(0xffffffffu, pm1, 2));
        float mn0 = fmaxf(m0, pm0), mn1 = fmaxf(m1, pm1);
        float al0 = ex2f(m0 - mn0), al1 = ex2f(m1 - mn1);
        m0 = mn0; m1 = mn1;
        float sum0 = 0.f, sum1 = 0.f;
#pragma unroll
        for (int nt = 0; nt < 8; nt++) {
            accS[nt][0] = ex2f(accS[nt][0] - mn0);
            accS[nt][1] = ex2f(accS[nt][1] - mn0);
            accS[nt][2] = ex2f(accS[nt][2] - mn1);
            accS[nt][3] = ex2f(accS[nt][3] - mn1);
            sum0 += accS[nt][0] + accS[nt][1];
            sum1 += accS[nt][2] + accS[nt][3];
        }
        sum0 += __shfl_xor_sync(0xffffffffu, sum0, 1);
        sum0 += __shfl_xor_sync(0xffffffffu, sum0, 2);
        sum1 += __shfl_xor_sync(0xffffffffu, sum1, 1);
        sum1 += __shfl_xor_sync(0xffffffffu, sum1, 2);
        l0 = l0 * al0 + sum0;
        l1 = l1 * al1 + sum1;

#pragma unroll
        for (int nt = 0; nt < 8; nt++) {
            accO[nt][0] *= al0; accO[nt][1] *= al0;
            accO[nt][2] *= al1; accO[nt][3] *= al1;
        }
        const uint32_t bV = sb + stage_off(st) + AT_KTILE
                          + t * AT_VRB + (g << 2);
#pragma unroll
        for (int kc = 0; kc < 8; kc++) {
            float x0 = __shfl_sync(0xffffffffu, accS[kc][0], src_lo);
            float x1 = __shfl_sync(0xffffffffu, accS[kc][1], src_lo);
            float y0 = __shfl_sync(0xffffffffu, accS[kc][0], src_hi);
            float y1 = __shfl_sync(0xffffffffu, accS[kc][1], src_hi);
            float z0 = __shfl_sync(0xffffffffu, accS[kc][2], src_lo);
            float z1 = __shfl_sync(0xffffffffu, accS[kc][3], src_lo);
            float u0 = __shfl_sync(0xffffffffu, accS[kc][2], src_hi);
            float u1 = __shfl_sync(0xffffffffu, accS[kc][3], src_hi);
            uint32_t a_[4];
            a_[0] = __float_as_uint((t & 1) ? x1 : x0);
            a_[1] = __float_as_uint((t & 1) ? z1 : z0);
            a_[2] = __float_as_uint((t & 1) ? y1 : y0);
            a_[3] = __float_as_uint((t & 1) ? u1 : u0);
#pragma unroll
            for (int nt = 0; nt < 8; nt++) {
                uint32_t b_[2];
                uint32_t ba = bV + kc * 8 * AT_VRB + (nt << 5);
                b_[0] = lds32(ba);
                b_[1] = lds32(ba + 4 * AT_VRB);
                mma_tf32(accO[nt], a_, b_);
            }
        }
    }

    {
        const int r0 = w16 + g, r1 = r0 + 8;
        float inv0 = 1.0f / l0;
        float inv1 = 1.0f / l1;
        __nv_bfloat16* obase = ctx + (size_t)b * SEQ * DIM + h * HDIM;
        __nv_bfloat16* o0 = &obase[(size_t)(qt * 64 + r0) * DIM];
        __nv_bfloat16* o1 = &obase[(size_t)(qt * 64 + r1) * DIM];
#pragma unroll
        for (int nt = 0; nt < 8; nt++) {
            int c = nt * 8 + (t << 1);
            *(__nv_bfloat162*)&o0[c] =
                __floats2bfloat162_rn(accO[nt][0] * inv0, accO[nt][1] * inv0);
            *(__nv_bfloat162*)&o1[c] =
                __floats2bfloat162_rn(accO[nt][2] * inv1, accO[nt][3] * inv1);
        }
    }
}

// ---------------- launch ------------------------------------------------------
template<typename T>
static T* dev_ptr_t(const void* sym)
{
    void* p = nullptr;
    cudaGetSymbolAddress(&p, sym);
    return (T*)p;
}

extern "C" void kernel_launch(void* const* d_in, const int* in_sizes, int n_in,
                              void* d_out, int out_size)
{
    (void)in_sizes; (void)n_in; (void)out_size;
    const float* x   = (const float*)d_in[0];
    const float* wq  = (const float*)d_in[1];
    const float* wk  = (const float*)d_in[2];
    const float* wv  = (const float*)d_in[3];
    const float* wo  = (const float*)d_in[4];
    const float* bo  = (const float*)d_in[5];
    const float* w1  = (const float*)d_in[6];
    const float* b1  = (const float*)d_in[7];
    const float* w2  = (const float*)d_in[8];
    const float* b2  = (const float*)d_in[9];
    const float* g1  = (const float*)d_in[10];
    const float* be1 = (const float*)d_in[11];
    const float* g2  = (const float*)d_in[12];
    const float* be2 = (const float*)d_in[13];
    float* out = (float*)d_out;

    __nv_bfloat16* hb  = dev_ptr_t<__nv_bfloat16>(g_hb);
    float* qb          = dev_ptr_t<float>(g_q);
    float* kb          = dev_ptr_t<float>(g_k);
    float* vb          = dev_ptr_t<float>(g_v);
    __nv_bfloat16* ctxb = dev_ptr_t<__nv_bfloat16>(g_ctxb);
    float* x1          = dev_ptr_t<float>(g_x1);
    __nv_bfloat16* ffb = dev_ptr_t<__nv_bfloat16>(g_ffb);
    __nv_bfloat16* wqT = dev_ptr_t<__nv_bfloat16>(g_wqT);
    __nv_bfloat16* wkT = dev_ptr_t<__nv_bfloat16>(g_wkT);
    __nv_bfloat16* wvT = dev_ptr_t<__nv_bfloat16>(g_wvT);
    __nv_bfloat16* woT = dev_ptr_t<__nv_bfloat16>(g_woT);
    __nv_bfloat16* w1T = dev_ptr_t<__nv_bfloat16>(g_w1T);
    __nv_bfloat16* w2T = dev_ptr_t<__nv_bfloat16>(g_w2T);

    cudaFuncSetAttribute(attn_mma_kernel, cudaFuncAttributeMaxDynamicSharedMemorySize, ATTN_SMEM);
    cudaFuncSetAttribute(qkv_gemm_kernel,
                         cudaFuncAttributeMaxDynamicSharedMemorySize, GEMM_SMEM);
    cudaFuncSetAttribute(bf16_gemm_kernel<false, true, true, false>,
                         cudaFuncAttributeMaxDynamicSharedMemorySize, GEMM_SMEM);
    cudaFuncSetAttribute(bf16_gemm_kernel<true, true, false, true>,
                         cudaFuncAttributeMaxDynamicSharedMemorySize, GEMM_SMEM);

    // prologue: weight transposes + LN1 in one launch
    prologue_kernel<<<1728 + NTOK / 8, 256>>>(x, g1, be1, hb,
                                              wq, wk, wv, wo, w1, w2,
                                              wqT, wkT, wvT, woT, w1T, w2T);
    // fused QKV projections
    qkv_gemm_kernel<<<dim3(NTOK / 128, 9), 256, GEMM_SMEM>>>(hb, wqT, wkT, wvT, qb, kb, vb);
    // attention
    attn_mma_kernel<<<dim3(SEQ / 64, NHEAD, BATCH), 128, ATTN_SMEM>>>(qb, kb, vb, ctxb);
    // output projection + residual
    bf16_gemm_kernel<false, true, true, false><<<dim3(NTOK / 128, 3), 256, GEMM_SMEM>>>(
        ctxb, woT, bo, x, x1, DIM, DIM);
    // LN2
    ln_kernel<<<NTOK / 8, 256>>>(x1, g2, be2, hb);
    // FFN1 (ReLU, bf16 out)
    bf16_gemm_kernel<true, true, false, true><<<dim3(NTOK / 128, 12), 256, GEMM_SMEM>>>(
        hb, w1T, b1, nullptr, ffb, DIM, FFDIM);
    // FFN2 (+residual)
    bf16_gemm_kernel<false, true, true, false><<<dim3(NTOK / 128, 3), 256, GEMM_SMEM>>>(
        ffb, w2T, b2, x1, out, FFDIM, DIM);
}